// round 6
// baseline (speedup 1.0000x reference)
#include <cuda_runtime.h>

#define NNODES_C 10000
#define NEDGES_C 160000
typedef unsigned long long u64;

__device__ float g_nodeftr[NNODES_C * 20];
__device__ float g_tmp[NEDGES_C * 20];

static __device__ __forceinline__ u64 pack2(float x) {
    u64 r;
    asm("mov.b64 %0, {%1, %1};" : "=l"(r) : "r"(__float_as_uint(x)));
    return r;
}
static __device__ __forceinline__ float2 unpack2(u64 v) {
    float lo, hi;
    asm("mov.b64 {%0, %1}, %2;" : "=f"(lo), "=f"(hi) : "l"(v));
    return make_float2(lo, hi);
}
static __device__ __forceinline__ u64 fma2(u64 a, u64 b, u64 c) {
    u64 d;
    asm("fma.rn.f32x2 %0, %1, %2, %3;" : "=l"(d) : "l"(a), "l"(b), "l"(c));
    return d;
}
static __device__ __forceinline__ void red4(float* p, float a, float b, float c, float d) {
    asm volatile("red.global.add.v4.f32 [%0], {%1, %2, %3, %4};"
                 :: "l"(p), "f"(a), "f"(b), "f"(c), "f"(d) : "memory");
}

__global__ void zero_nf_kernel(int n4) {
    int i = blockIdx.x * blockDim.x + threadIdx.x;
    if (i < n4) ((float4*)g_nodeftr)[i] = make_float4(0.f, 0.f, 0.f, 0.f);
}

// tp1 smem (floats): [0,160) W1 | [160,9376) W2 | [9376, +128*73) scratch
#define TP1_SMEM_FLOATS (160 + 9216 + 128*73)
#define SCR1 73

// ============================ Kernel A: MLP1 + TP1 + gating (2 edges/thread) ============================
__global__ __launch_bounds__(128, 2) void edge_tp1_kernel(
    const float* __restrict__ hn, const float* __restrict__ he,
    const int* __restrict__ esrc, const int* __restrict__ edst,
    const float* __restrict__ evec, const float* __restrict__ emb,
    const float* __restrict__ fcW1, const float* __restrict__ fcW2, int E)
{
    const float SQ3f    = 1.7320508075688772f;
    const float INVSQ3f = 0.57735026918962576f;
    const float RS10    = 0.31622776601683794f;
    const float CS1     = 0.14433756729740645f;   // 1/sqrt(48)
    const float CV1     = 0.20412414523193150f;   // 1/sqrt(24)

    extern __shared__ __align__(16) float smem[];
    float* sW1 = smem;
    float* sW2 = smem + 160;
    float* scr = smem + 9376;

    {
        const float4* g1 = (const float4*)fcW1;
        float4* d1 = (float4*)sW1;
        for (int t = threadIdx.x; t < 40; t += 128) {
            float4 a = g1[t]; d1[t] = make_float4(a.x*RS10, a.y*RS10, a.z*RS10, a.w*RS10);
        }
        const float4* g2 = (const float4*)fcW2;
        float4* d2 = (float4*)sW2;
        const float sS = CS1 * 0.25f, sV = CV1 * 0.25f;
        for (int t = threadIdx.x; t < 2304; t += 128) {
            int c0 = (t*4) % 576;
            float sc = (c0 < 288) ? sS : (c0 < 432) ? sV : (c0 < 528) ? sS : sV;
            float4 a = g2[t]; d2[t] = make_float4(a.x*sc, a.y*sc, a.z*sc, a.w*sc);
        }
    }
    __syncthreads();

    int tid = threadIdx.x;
    int base = blockIdx.x * 256;
    int e0 = base + tid;
    if (e0 >= E) return;
    int e1 = base + 128 + tid;
    bool v1 = (e1 < E);
    int e1c = v1 ? e1 : e0;

    float* myscr = scr + tid * SCR1;

    const ulonglong2* W2 = (const ulonglong2*)sW2;   // 144 chunks per k-row

    u64 h1p[2][16];
    u64 a1p[2][2][3];
    float sh1[2][3];

    // ---- per-edge prologue: gather, dots, MLP1, vv ----
#pragma unroll
    for (int j = 0; j < 2; j++) {
        int e = j ? e1c : e0;
        int srcI = esrc[e], dstI = edst[e];
        float vf[36];
        {
            float4 r0[5], r1[5], r2[5];
            const float4* p = (const float4*)(he + (size_t)e*20);
#pragma unroll
            for (int i = 0; i < 5; i++) r0[i] = p[i];
            const float4* ps = (const float4*)(hn + (size_t)srcI*20);
#pragma unroll
            for (int i = 0; i < 5; i++) r1[i] = ps[i];
            const float4* pd = (const float4*)(hn + (size_t)dstI*20);
#pragma unroll
            for (int i = 0; i < 5; i++) r2[i] = pd[i];
            const float* re = (const float*)r0;
            const float* rs = (const float*)r1;
            const float* rd = (const float*)r2;
#pragma unroll
            for (int q = 0; q < 8; q++) {
                myscr[j*36 + q]      = re[q];
                myscr[j*36 + 8 + q]  = rs[q];
                myscr[j*36 + 16 + q] = rd[q];
            }
#pragma unroll
            for (int q = 0; q < 12; q++) { vf[q] = re[8+q]; vf[12+q] = rs[8+q]; vf[24+q] = rd[8+q]; }
        }
        {
            float ex = evec[e*3+0], ey = evec[e*3+1], ez = evec[e*3+2];
            float nn = sqrtf(ex*ex + ey*ey + ez*ez) + 1e-12f;
            float f = SQ3f / nn;
            sh1[j][0] = ex*f; sh1[j][1] = ey*f; sh1[j][2] = ez*f;
        }
#pragma unroll
        for (int i = 0; i < 12; i++)
            myscr[j*36 + 24 + i] =
                (vf[i*3+0]*sh1[j][0] + vf[i*3+1]*sh1[j][1] + vf[i*3+2]*sh1[j][2]) * INVSQ3f;

        // MLP1
        {
            float embr[10];
            const float2* pe2 = (const float2*)(emb + (size_t)e*10);
#pragma unroll
            for (int q = 0; q < 5; q++) { float2 t = pe2[q]; embr[2*q] = t.x; embr[2*q+1] = t.y; }
            const ulonglong2* W = (const ulonglong2*)sW1;
            u64 acc[8];
#pragma unroll
            for (int p = 0; p < 8; p++) acc[p] = 0ull;
#pragma unroll
            for (int q = 0; q < 10; q++) {
                u64 ej = pack2(embr[q]);
#pragma unroll
                for (int g = 0; g < 4; g++) {
                    ulonglong2 w = W[q*4+g];
                    acc[2*g]   = fma2(ej, w.x, acc[2*g]);
                    acc[2*g+1] = fma2(ej, w.y, acc[2*g+1]);
                }
            }
#pragma unroll
            for (int p = 0; p < 8; p++) {
                float2 f = unpack2(acc[p]);
                h1p[j][2*p]   = pack2(fmaxf(f.x, 0.f));
                h1p[j][2*p+1] = pack2(fmaxf(f.y, 0.f));
            }
        }

        // vv (unrolled, consumes vf)
#pragma unroll
        for (int c = 0; c < 3; c++) { a1p[j][0][c] = 0ull; a1p[j][1][c] = 0ull; }
#pragma unroll
        for (int i = 0; i < 12; i++) {
            u64 aA = 0ull, aB = 0ull;
#pragma unroll
            for (int k = 0; k < 16; k++) {
                ulonglong2 w = W2[k*144 + 132 + i];
                aA = fma2(h1p[j][k], w.x, aA);
                aB = fma2(h1p[j][k], w.y, aB);
            }
#pragma unroll
            for (int c = 0; c < 3; c++) {
                u64 vc2 = pack2(vf[i*3+c]);
                a1p[j][0][c] = fma2(vc2, aA, a1p[j][0][c]);
                a1p[j][1][c] = fma2(vc2, aB, a1p[j][1][c]);
            }
        }
    }

    // ---- vs: chunk 72 + i*3 + g ----
    u64 a0vp[2][6];
#pragma unroll
    for (int p = 0; p < 6; p++) { a0vp[0][p] = 0ull; a0vp[1][p] = 0ull; }
#pragma unroll 1
    for (int i = 0; i < 12; i++) {
        u64 d0 = pack2(myscr[24+i]);
        u64 d1 = pack2(myscr[60+i]);
        const ulonglong2* Wb = W2 + 72 + i*3;
#pragma unroll
        for (int g = 0; g < 3; g++) {
            u64 aA0 = 0ull, aB0 = 0ull, aA1 = 0ull, aB1 = 0ull;
#pragma unroll
            for (int k = 0; k < 16; k++) {
                ulonglong2 w = Wb[k*144 + g];
                aA0 = fma2(h1p[0][k], w.x, aA0);
                aB0 = fma2(h1p[0][k], w.y, aB0);
                aA1 = fma2(h1p[1][k], w.x, aA1);
                aB1 = fma2(h1p[1][k], w.y, aB1);
            }
            a0vp[0][2*g]   = fma2(d0, aA0, a0vp[0][2*g]);
            a0vp[0][2*g+1] = fma2(d0, aB0, a0vp[0][2*g+1]);
            a0vp[1][2*g]   = fma2(d1, aA1, a0vp[1][2*g]);
            a0vp[1][2*g+1] = fma2(d1, aB1, a0vp[1][2*g+1]);
        }
    }

    // ---- ss: chunk i*3 + g ----
    u64 a0sp[2][6];
#pragma unroll
    for (int p = 0; p < 6; p++) { a0sp[0][p] = 0ull; a0sp[1][p] = 0ull; }
#pragma unroll 1
    for (int i = 0; i < 24; i++) {
        u64 s0 = pack2(myscr[i]);
        u64 s1 = pack2(myscr[36+i]);
        const ulonglong2* Wb = W2 + i*3;
#pragma unroll
        for (int g = 0; g < 3; g++) {
            u64 aA0 = 0ull, aB0 = 0ull, aA1 = 0ull, aB1 = 0ull;
#pragma unroll
            for (int k = 0; k < 16; k++) {
                ulonglong2 w = Wb[k*144 + g];
                aA0 = fma2(h1p[0][k], w.x, aA0);
                aB0 = fma2(h1p[0][k], w.y, aB0);
                aA1 = fma2(h1p[1][k], w.x, aA1);
                aB1 = fma2(h1p[1][k], w.y, aB1);
            }
            a0sp[0][2*g]   = fma2(s0, aA0, a0sp[0][2*g]);
            a0sp[0][2*g+1] = fma2(s0, aB0, a0sp[0][2*g+1]);
            a0sp[1][2*g]   = fma2(s1, aA1, a0sp[1][2*g]);
            a0sp[1][2*g+1] = fma2(s1, aB1, a0sp[1][2*g+1]);
        }
    }

    // ---- sv: chunk 108 + i ----
    u64 asvp[2][2];
    asvp[0][0] = 0ull; asvp[0][1] = 0ull; asvp[1][0] = 0ull; asvp[1][1] = 0ull;
#pragma unroll 1
    for (int i = 0; i < 24; i++) {
        u64 aA0 = 0ull, aB0 = 0ull, aA1 = 0ull, aB1 = 0ull;
        const ulonglong2* Wb = W2 + 108 + i;
#pragma unroll
        for (int k = 0; k < 16; k++) {
            ulonglong2 w = Wb[k*144];
            aA0 = fma2(h1p[0][k], w.x, aA0);
            aB0 = fma2(h1p[0][k], w.y, aB0);
            aA1 = fma2(h1p[1][k], w.x, aA1);
            aB1 = fma2(h1p[1][k], w.y, aB1);
        }
        u64 s0 = pack2(myscr[i]);
        u64 s1 = pack2(myscr[36+i]);
        asvp[0][0] = fma2(s0, aA0, asvp[0][0]);
        asvp[0][1] = fma2(s0, aB0, asvp[0][1]);
        asvp[1][0] = fma2(s1, aA1, asvp[1][0]);
        asvp[1][1] = fma2(s1, aB1, asvp[1][1]);
    }

    // ---- gating -> g_tmp (scales folded into weights) ----
#pragma unroll
    for (int j = 0; j < 2; j++) {
        if (j == 1 && !v1) break;
        int e = j ? e1 : e0;
        float outr[20];
        float a0[12], asv[4], a1[4][3];
#pragma unroll
        for (int p = 0; p < 6; p++) {
            float2 fs = unpack2(a0sp[j][p]);
            float2 fv = unpack2(a0vp[j][p]);
            a0[2*p]   = fs.x + fv.x;
            a0[2*p+1] = fs.y + fv.y;
        }
        {
            float2 f0 = unpack2(asvp[j][0]); float2 f1 = unpack2(asvp[j][1]);
            asv[0] = f0.x; asv[1] = f0.y; asv[2] = f1.x; asv[3] = f1.y;
        }
#pragma unroll
        for (int c = 0; c < 3; c++) {
            float2 f0 = unpack2(a1p[j][0][c]); float2 f1 = unpack2(a1p[j][1][c]);
            a1[0][c] = f0.x; a1[1][c] = f0.y; a1[2][c] = f1.x; a1[3][c] = f1.y;
        }
#pragma unroll
        for (int o = 0; o < 8; o++) outr[o] = fmaxf(a0[o], 0.f);
#pragma unroll
        for (int o = 0; o < 4; o++) {
            float gate = fmaxf(a0[8+o], 0.f);
#pragma unroll
            for (int c = 0; c < 3; c++)
                outr[8 + o*3 + c] = (asv[o]*sh1[j][c] + a1[o][c]) * gate;
        }
        float4* tp = (float4*)(g_tmp + (size_t)e*20);
        const float4* sp = (const float4*)outr;
#pragma unroll
        for (int t = 0; t < 5; t++) tp[t] = sp[t];
    }
}

// ============================ Kernel B: MLP2 + TP2 + epilogue (2 edges/thread) ============================
#define SCR2 25

__global__ __launch_bounds__(128, 2) void edge_tp2_kernel(
    const float* __restrict__ he,
    const int* __restrict__ edst, const float* __restrict__ evec,
    const float* __restrict__ emb, const float* __restrict__ enorm,
    const float* __restrict__ fc2W1, const float* __restrict__ fc2W2,
    float* __restrict__ out_he, int E)
{
    const float SQ3f    = 1.7320508075688772f;
    const float INVSQ3f = 0.57735026918962576f;
    const float RS10    = 0.31622776601683794f;
    const float CS2     = 0.25f;
    const float CV2     = 0.35355339059327379f;

    __shared__ __align__(16) float sW1b[160];
    __shared__ __align__(16) float sW2b[2304];
    __shared__ __align__(16) float scr2[128 * SCR2];
    {
        const float4* g1b = (const float4*)fc2W1;
        float4* d1b = (float4*)sW1b;
        for (int t = threadIdx.x; t < 40; t += 128) {
            float4 b = g1b[t]; d1b[t] = make_float4(b.x*RS10, b.y*RS10, b.z*RS10, b.w*RS10);
        }
        const float4* g2b = (const float4*)fc2W2;
        float4* d2b = (float4*)sW2b;
        const float sS = CS2 * 0.25f, sV = CV2 * 0.25f;
        for (int t = threadIdx.x; t < 576; t += 128) {
            int c0 = (t*4) % 144;
            float sc = (c0 < 64) ? sS : (c0 < 96) ? sV : (c0 < 128) ? sS : sV;
            float4 a = g2b[t]; d2b[t] = make_float4(a.x*sc, a.y*sc, a.z*sc, a.w*sc);
        }
    }
    __syncthreads();

    int tid = threadIdx.x;
    int base = blockIdx.x * 256;
    int e0 = base + tid;
    if (e0 >= E) return;
    int e1 = base + 128 + tid;
    bool v1 = (e1 < E);
    int e1c = v1 ? e1 : e0;

    float* myscr = scr2 + tid * SCR2;   // [0,8) ts0 | [8,12) dt0 | [12,20) ts1 | [20,24) dt1

    const ulonglong2* W2b = (const ulonglong2*)sW2b;  // 36 chunks per k-row

    u64 h2p[2][16];
    u64 b1p[2][2][3];
    float sh1[2][3];
    float tv[2][12];

    // ---- per-edge prologue: load gated, sh1, dt, MLP2, vv ----
#pragma unroll
    for (int j = 0; j < 2; j++) {
        int e = j ? e1c : e0;
        {
            float4 r[5];
            const float4* tp = (const float4*)(g_tmp + (size_t)e*20);
#pragma unroll
            for (int i = 0; i < 5; i++) r[i] = tp[i];
            const float* f = (const float*)r;
#pragma unroll
            for (int q = 0; q < 8; q++) myscr[j*12 + q] = f[q];
#pragma unroll
            for (int q = 0; q < 12; q++) tv[j][q] = f[8+q];
        }
        {
            float ex = evec[e*3+0], ey = evec[e*3+1], ez = evec[e*3+2];
            float nn = sqrtf(ex*ex + ey*ey + ez*ez) + 1e-12f;
            float f = SQ3f / nn;
            sh1[j][0] = ex*f; sh1[j][1] = ey*f; sh1[j][2] = ez*f;
        }
#pragma unroll
        for (int i = 0; i < 4; i++)
            myscr[j*12 + 8 + i] =
                (tv[j][i*3+0]*sh1[j][0] + tv[j][i*3+1]*sh1[j][1] + tv[j][i*3+2]*sh1[j][2]) * INVSQ3f;

        // MLP2
        {
            float embr[10];
            const float2* pe2 = (const float2*)(emb + (size_t)e*10);
#pragma unroll
            for (int q = 0; q < 5; q++) { float2 t = pe2[q]; embr[2*q] = t.x; embr[2*q+1] = t.y; }
            const ulonglong2* W = (const ulonglong2*)sW1b;
            u64 acc[8];
#pragma unroll
            for (int p = 0; p < 8; p++) acc[p] = 0ull;
#pragma unroll
            for (int q = 0; q < 10; q++) {
                u64 ej = pack2(embr[q]);
#pragma unroll
                for (int g = 0; g < 4; g++) {
                    ulonglong2 w = W[q*4+g];
                    acc[2*g]   = fma2(ej, w.x, acc[2*g]);
                    acc[2*g+1] = fma2(ej, w.y, acc[2*g+1]);
                }
            }
#pragma unroll
            for (int p = 0; p < 8; p++) {
                float2 f = unpack2(acc[p]);
                h2p[j][2*p]   = pack2(fmaxf(f.x, 0.f));
                h2p[j][2*p+1] = pack2(fmaxf(f.y, 0.f));
            }
        }

        // vv: chunk 32 + i (consumes tv as multiplier)
#pragma unroll
        for (int c = 0; c < 3; c++) { b1p[j][0][c] = 0ull; b1p[j][1][c] = 0ull; }
#pragma unroll
        for (int i = 0; i < 4; i++) {
            u64 aA = 0ull, aB = 0ull;
#pragma unroll
            for (int k = 0; k < 16; k++) {
                ulonglong2 w = W2b[k*36 + 32 + i];
                aA = fma2(h2p[j][k], w.x, aA);
                aB = fma2(h2p[j][k], w.y, aB);
            }
#pragma unroll
            for (int c = 0; c < 3; c++) {
                u64 vc2 = pack2(tv[j][i*3+c]);
                b1p[j][0][c] = fma2(vc2, aA, b1p[j][0][c]);
                b1p[j][1][c] = fma2(vc2, aB, b1p[j][1][c]);
            }
        }
    }

    // ---- ss: chunk i*2 + g ----
    u64 b0sp[2][4];
#pragma unroll
    for (int p = 0; p < 4; p++) { b0sp[0][p] = 0ull; b0sp[1][p] = 0ull; }
#pragma unroll 1
    for (int i = 0; i < 8; i++) {
        u64 s0 = pack2(myscr[i]);
        u64 s1 = pack2(myscr[12+i]);
        const ulonglong2* Wb = W2b + i*2;
#pragma unroll
        for (int g = 0; g < 2; g++) {
            u64 aA0 = 0ull, aB0 = 0ull, aA1 = 0ull, aB1 = 0ull;
#pragma unroll
            for (int k = 0; k < 16; k++) {
                ulonglong2 w = Wb[k*36 + g];
                aA0 = fma2(h2p[0][k], w.x, aA0);
                aB0 = fma2(h2p[0][k], w.y, aB0);
                aA1 = fma2(h2p[1][k], w.x, aA1);
                aB1 = fma2(h2p[1][k], w.y, aB1);
            }
            b0sp[0][2*g]   = fma2(s0, aA0, b0sp[0][2*g]);
            b0sp[0][2*g+1] = fma2(s0, aB0, b0sp[0][2*g+1]);
            b0sp[1][2*g]   = fma2(s1, aA1, b0sp[1][2*g]);
            b0sp[1][2*g+1] = fma2(s1, aB1, b0sp[1][2*g+1]);
        }
    }
    // ---- vs: chunk 16 + i*2 + g ----
    u64 b0vp[2][4];
#pragma unroll
    for (int p = 0; p < 4; p++) { b0vp[0][p] = 0ull; b0vp[1][p] = 0ull; }
#pragma unroll 1
    for (int i = 0; i < 4; i++) {
        u64 d0 = pack2(myscr[8+i]);
        u64 d1 = pack2(myscr[20+i]);
        const ulonglong2* Wb = W2b + 16 + i*2;
#pragma unroll
        for (int g = 0; g < 2; g++) {
            u64 aA0 = 0ull, aB0 = 0ull, aA1 = 0ull, aB1 = 0ull;
#pragma unroll
            for (int k = 0; k < 16; k++) {
                ulonglong2 w = Wb[k*36 + g];
                aA0 = fma2(h2p[0][k], w.x, aA0);
                aB0 = fma2(h2p[0][k], w.y, aB0);
                aA1 = fma2(h2p[1][k], w.x, aA1);
                aB1 = fma2(h2p[1][k], w.y, aB1);
            }
            b0vp[0][2*g]   = fma2(d0, aA0, b0vp[0][2*g]);
            b0vp[0][2*g+1] = fma2(d0, aB0, b0vp[0][2*g+1]);
            b0vp[1][2*g]   = fma2(d1, aA1, b0vp[1][2*g]);
            b0vp[1][2*g+1] = fma2(d1, aB1, b0vp[1][2*g+1]);
        }
    }
    // ---- sv: chunk 24 + i ----
    u64 bsvp[2][2];
    bsvp[0][0] = 0ull; bsvp[0][1] = 0ull; bsvp[1][0] = 0ull; bsvp[1][1] = 0ull;
#pragma unroll 1
    for (int i = 0; i < 8; i++) {
        u64 aA0 = 0ull, aB0 = 0ull, aA1 = 0ull, aB1 = 0ull;
        const ulonglong2* Wb = W2b + 24 + i;
#pragma unroll
        for (int k = 0; k < 16; k++) {
            ulonglong2 w = Wb[k*36];
            aA0 = fma2(h2p[0][k], w.x, aA0);
            aB0 = fma2(h2p[0][k], w.y, aB0);
            aA1 = fma2(h2p[1][k], w.x, aA1);
            aB1 = fma2(h2p[1][k], w.y, aB1);
        }
        u64 s0 = pack2(myscr[i]);
        u64 s1 = pack2(myscr[12+i]);
        bsvp[0][0] = fma2(s0, aA0, bsvp[0][0]);
        bsvp[0][1] = fma2(s0, aB0, bsvp[0][1]);
        bsvp[1][0] = fma2(s1, aA1, bsvp[1][0]);
        bsvp[1][1] = fma2(s1, aB1, bsvp[1][1]);
    }

    // ---- epilogue per edge ----
#pragma unroll
    for (int j = 0; j < 2; j++) {
        if (j == 1 && !v1) break;
        int e = j ? e1 : e0;
        float b0[8], bsv[4], b1[4][3];
#pragma unroll
        for (int p = 0; p < 4; p++) {
            float2 fs = unpack2(b0sp[j][p]);
            float2 fv = unpack2(b0vp[j][p]);
            b0[2*p]   = fs.x + fv.x;
            b0[2*p+1] = fs.y + fv.y;
        }
        {
            float2 f0 = unpack2(bsvp[j][0]); float2 f1 = unpack2(bsvp[j][1]);
            bsv[0] = f0.x; bsv[1] = f0.y; bsv[2] = f1.x; bsv[3] = f1.y;
        }
#pragma unroll
        for (int c = 0; c < 3; c++) {
            float2 f0 = unpack2(b1p[j][0][c]); float2 f1 = unpack2(b1p[j][1][c]);
            b1[0][c] = f0.x; b1[1][c] = f0.y; b1[2][c] = f1.x; b1[3][c] = f1.y;
        }

        float hnew[20];
        {
            float4 r[5];
            const float4* p = (const float4*)(he + (size_t)e*20);
#pragma unroll
            for (int i = 0; i < 5; i++) r[i] = p[i];
            const float* re = (const float*)r;
#pragma unroll
            for (int q = 0; q < 8; q++) hnew[q] = re[q] + b0[q];
#pragma unroll
            for (int o = 0; o < 4; o++)
#pragma unroll
                for (int c = 0; c < 3; c++)
                    hnew[8 + o*3 + c] = re[8+o*3+c] + (bsv[o]*sh1[j][c] + b1[o][c]);
        }
        {
            float4* op = (float4*)(out_he + (size_t)e*20);
            const float4* hp = (const float4*)hnew;
#pragma unroll
            for (int t = 0; t < 5; t++) op[t] = hp[t];
        }
        int dstI = edst[e];
        float nw = enorm[e];
        float* nf = &g_nodeftr[(size_t)dstI*20];
#pragma unroll
        for (int t = 0; t < 5; t++)
            red4(nf + t*4, hnew[t*4]*nw, hnew[t*4+1]*nw, hnew[t*4+2]*nw, hnew[t*4+3]*nw);
    }
}

// ============================ node kernel ============================
__global__ __launch_bounds__(64) void node_kernel(
    const float* __restrict__ hn,
    const float* __restrict__ WgS, const float* __restrict__ WgV,
    const float* __restrict__ WoS, const float* __restrict__ WoV,
    float* __restrict__ out_hn, int N)
{
    const float RS8 = 0.35355339059327379f;
    int n = blockIdx.x*64 + threadIdx.x;
    if (n >= N) return;

    float cs[16], cv[8][3];
    const float* ph = hn + (size_t)n*20;
    const float* pf = g_nodeftr + (size_t)n*20;
#pragma unroll
    for (int j = 0; j < 8; j++) { cs[j] = ph[j]; cs[8+j] = pf[j]; }
#pragma unroll
    for (int i = 0; i < 4; i++)
#pragma unroll
        for (int c = 0; c < 3; c++) { cv[i][c] = ph[8+i*3+c]; cv[4+i][c] = pf[8+i*3+c]; }

    float gl[12];
#pragma unroll
    for (int o = 0; o < 12; o++) {
        float a = 0.f;
#pragma unroll
        for (int i = 0; i < 16; i++) a = fmaf(cs[i], __ldg(&WgS[i*12+o]), a);
        gl[o] = a * 0.25f;
    }
    float vl[4][3];
#pragma unroll
    for (int o = 0; o < 4; o++)
#pragma unroll
        for (int c = 0; c < 3; c++) {
            float a = 0.f;
#pragma unroll
            for (int i = 0; i < 8; i++) a = fmaf(cv[i][c], __ldg(&WgV[i*4+o]), a);
            vl[o][c] = a * RS8;
        }

    float ls[8], lg[4];
#pragma unroll
    for (int j = 0; j < 8; j++) ls[j] = fmaxf(gl[j], 0.f);
#pragma unroll
    for (int o = 0; o < 4; o++) lg[o] = fmaxf(gl[8+o], 0.f);

    float lv[4][3];
#pragma unroll
    for (int o = 0; o < 4; o++)
#pragma unroll
        for (int c = 0; c < 3; c++) lv[o][c] = vl[o][c] * lg[o];

    float os_[8];
#pragma unroll
    for (int o = 0; o < 8; o++) {
        float a = 0.f;
#pragma unroll
        for (int i = 0; i < 8; i++) a = fmaf(ls[i], __ldg(&WoS[i*8+o]), a);
        os_[o] = a * RS8;
    }
    float ov[4][3];
#pragma unroll
    for (int o = 0; o < 4; o++)
#pragma unroll
        for (int c = 0; c < 3; c++) {
            float a = 0.f;
#pragma unroll
            for (int i = 0; i < 4; i++) a = fmaf(lv[i][c], __ldg(&WoV[i*4+o]), a);
            ov[o][c] = a * 0.5f;
        }

    float* po = out_hn + (size_t)n*20;
#pragma unroll
    for (int j = 0; j < 8; j++) po[j] = ph[j] + os_[j];
#pragma unroll
    for (int o = 0; o < 4; o++)
#pragma unroll
        for (int c = 0; c < 3; c++) po[8+o*3+c] = ph[8+o*3+c] + ov[o][c];
}

extern "C" void kernel_launch(void* const* d_in, const int* in_sizes, int n_in,
                              void* d_out, int out_size) {
    const float* hn    = (const float*)d_in[0];
    const float* he    = (const float*)d_in[1];
    const int*   esrc  = (const int*)d_in[2];
    const int*   edst  = (const int*)d_in[3];
    const float* evec  = (const float*)d_in[4];
    const float* emb   = (const float*)d_in[5];
    const float* enorm = (const float*)d_in[6];
    const float* fcW1  = (const float*)d_in[8];
    const float* fcW2  = (const float*)d_in[9];
    const float* fc2W1 = (const float*)d_in[10];
    const float* fc2W2 = (const float*)d_in[11];
    const float* WgS   = (const float*)d_in[12];
    const float* WgV   = (const float*)d_in[13];
    const float* WoS   = (const float*)d_in[14];
    const float* WoV   = (const float*)d_in[15];

    int N = in_sizes[0] / 20;
    int E = in_sizes[1] / 20;

    float* out    = (float*)d_out;
    float* out_hn = out;                      // (N,20) first
    float* out_he = out + (size_t)N * 20;     // (E,20) second

    size_t tp1_smem = TP1_SMEM_FLOATS * sizeof(float);
    cudaFuncSetAttribute(edge_tp1_kernel,
                         cudaFuncAttributeMaxDynamicSharedMemorySize, (int)tp1_smem);

    int n4 = (N * 20) / 4;
    int eblocks = (E + 255) / 256;
    zero_nf_kernel<<<(n4 + 255)/256, 256>>>(n4);
    edge_tp1_kernel<<<eblocks, 128, tp1_smem>>>(hn, he, esrc, edst, evec, emb, fcW1, fcW2, E);
    edge_tp2_kernel<<<eblocks, 128>>>(he, edst, evec, emb, enorm, fc2W1, fc2W2, out_he, E);
    node_kernel<<<(N + 63)/64, 64>>>(hn, WgS, WgV, WoS, WoV, out_hn, N);
}

// round 7
// speedup vs baseline: 1.2832x; 1.2832x over previous
#include <cuda_runtime.h>

#define NNODES_C 10000
#define NEDGES_C 160000
typedef unsigned long long u64;

__device__ float g_nodeftr[NNODES_C * 20];
__device__ float g_tmp[NEDGES_C * 20];

static __device__ __forceinline__ u64 pack2(float x) {
    u64 r;
    asm("mov.b64 %0, {%1, %1};" : "=l"(r) : "r"(__float_as_uint(x)));
    return r;
}
static __device__ __forceinline__ float2 unpack2(u64 v) {
    float lo, hi;
    asm("mov.b64 {%0, %1}, %2;" : "=f"(lo), "=f"(hi) : "l"(v));
    return make_float2(lo, hi);
}
static __device__ __forceinline__ u64 fma2(u64 a, u64 b, u64 c) {
    u64 d;
    asm("fma.rn.f32x2 %0, %1, %2, %3;" : "=l"(d) : "l"(a), "l"(b), "l"(c));
    return d;
}
static __device__ __forceinline__ void red4(float* p, float a, float b, float c, float d) {
    asm volatile("red.global.add.v4.f32 [%0], {%1, %2, %3, %4};"
                 :: "l"(p), "f"(a), "f"(b), "f"(c), "f"(d) : "memory");
}

__global__ void zero_nf_kernel(int n4) {
    int i = blockIdx.x * blockDim.x + threadIdx.x;
    if (i < n4) ((float4*)g_nodeftr)[i] = make_float4(0.f, 0.f, 0.f, 0.f);
}

// ============================ Kernel A: MLP1 + TP1 + gating ============================
__global__ __launch_bounds__(128, 4) void edge_tp1_kernel(
    const float* __restrict__ hn, const float* __restrict__ he,
    const int* __restrict__ esrc, const int* __restrict__ edst,
    const float* __restrict__ evec, const float* __restrict__ emb,
    const float* __restrict__ fcW1, const float* __restrict__ fcW2, int E)
{
    const float SQ3f    = 1.7320508075688772f;
    const float INVSQ3f = 0.57735026918962576f;
    const float RS10    = 0.31622776601683794f;
    const float CS1     = 0.14433756729740645f;   // 1/sqrt(48)
    const float CV1     = 0.20412414523193150f;   // 1/sqrt(24)

    __shared__ __align__(16) float sW1[160];
    __shared__ __align__(16) float sW2[9216];
    {
        const float4* g1 = (const float4*)fcW1;
        float4* d1 = (float4*)sW1;
        for (int t = threadIdx.x; t < 40; t += 128) {
            float4 a = g1[t]; d1[t] = make_float4(a.x*RS10, a.y*RS10, a.z*RS10, a.w*RS10);
        }
        const float4* g2 = (const float4*)fcW2;
        float4* d2 = (float4*)sW2;
        const float sS = CS1 * 0.25f, sV = CV1 * 0.25f;
        for (int t = threadIdx.x; t < 2304; t += 128) {
            int c0 = (t*4) % 576;
            float sc = (c0 < 288) ? sS : (c0 < 432) ? sV : (c0 < 528) ? sS : sV;
            float4 a = g2[t]; d2[t] = make_float4(a.x*sc, a.y*sc, a.z*sc, a.w*sc);
        }
    }
    __syncthreads();

    int e = blockIdx.x*128 + threadIdx.x;
    if (e >= E) return;

    // ---- gather ----
    int srcI = esrc[e], dstI = edst[e];
    float s[24], vf[36];
    {
        float4 r0[5], r1[5], r2[5];
        const float4* p = (const float4*)(he + (size_t)e*20);
#pragma unroll
        for (int i = 0; i < 5; i++) r0[i] = p[i];
        const float4* ps = (const float4*)(hn + (size_t)srcI*20);
#pragma unroll
        for (int i = 0; i < 5; i++) r1[i] = ps[i];
        const float4* pd = (const float4*)(hn + (size_t)dstI*20);
#pragma unroll
        for (int i = 0; i < 5; i++) r2[i] = pd[i];
        const float* re = (const float*)r0;
        const float* rs = (const float*)r1;
        const float* rd = (const float*)r2;
#pragma unroll
        for (int j = 0; j < 8; j++) { s[j] = re[j]; s[8+j] = rs[j]; s[16+j] = rd[j]; }
#pragma unroll
        for (int j = 0; j < 12; j++) { vf[j] = re[8+j]; vf[12+j] = rs[8+j]; vf[24+j] = rd[8+j]; }
    }

    float sh1[3];
    {
        float ex = evec[e*3+0], ey = evec[e*3+1], ez = evec[e*3+2];
        float nn = sqrtf(ex*ex + ey*ey + ez*ez) + 1e-12f;
        float f = SQ3f / nn;
        sh1[0] = ex*f; sh1[1] = ey*f; sh1[2] = ez*f;
    }
    float dots[12];
#pragma unroll
    for (int i = 0; i < 12; i++)
        dots[i] = (vf[i*3+0]*sh1[0] + vf[i*3+1]*sh1[1] + vf[i*3+2]*sh1[2]) * INVSQ3f;

    // ---- h1 = relu(emb @ fcW1/sqrt(10)) ----
    u64 h1p[16];
    {
        float embr[10];
        const float2* pe2 = (const float2*)(emb + (size_t)e*10);
#pragma unroll
        for (int j = 0; j < 5; j++) { float2 t = pe2[j]; embr[2*j] = t.x; embr[2*j+1] = t.y; }
        const ulonglong2* W = (const ulonglong2*)sW1;
        u64 acc[8];
#pragma unroll
        for (int p = 0; p < 8; p++) acc[p] = 0ull;
#pragma unroll
        for (int j = 0; j < 10; j++) {
            u64 ej = pack2(embr[j]);
#pragma unroll
            for (int g = 0; g < 4; g++) {
                ulonglong2 w = W[j*4+g];
                acc[2*g]   = fma2(ej, w.x, acc[2*g]);
                acc[2*g+1] = fma2(ej, w.y, acc[2*g+1]);
            }
        }
#pragma unroll
        for (int p = 0; p < 8; p++) {
            float2 f = unpack2(acc[p]);
            h1p[2*p]   = pack2(fmaxf(f.x, 0.f));
            h1p[2*p+1] = pack2(fmaxf(f.y, 0.f));
        }
    }

    const ulonglong2* W2 = (const ulonglong2*)sW2;   // 144 chunks per k-row

    // ---- vv: chunk 132 + i  (unrolled; consumes vf, then vf dead) ----
    u64 a1p[2][3];
#pragma unroll
    for (int c = 0; c < 3; c++) { a1p[0][c] = 0ull; a1p[1][c] = 0ull; }
#pragma unroll
    for (int i = 0; i < 12; i++) {
        u64 aA = 0ull, aB = 0ull;
#pragma unroll
        for (int k = 0; k < 16; k++) {
            ulonglong2 w = W2[k*144 + 132 + i];
            aA = fma2(h1p[k], w.x, aA);
            aB = fma2(h1p[k], w.y, aB);
        }
#pragma unroll
        for (int c = 0; c < 3; c++) {
            u64 vc2 = pack2(vf[i*3+c]);
            a1p[0][c] = fma2(vc2, aA, a1p[0][c]);
            a1p[1][c] = fma2(vc2, aB, a1p[1][c]);
        }
    }

    // ---- vs: chunk 72 + i*3 + g  (rolled; dots local) ----
    u64 a0vp[6];
#pragma unroll
    for (int p = 0; p < 6; p++) a0vp[p] = 0ull;
#pragma unroll 1
    for (int i = 0; i < 12; i++) {
        u64 di2 = pack2(dots[i]);
        const ulonglong2* Wb = W2 + 72 + i*3;
#pragma unroll
        for (int g = 0; g < 3; g++) {
            u64 aA = 0ull, aB = 0ull;
#pragma unroll
            for (int k = 0; k < 16; k++) {
                ulonglong2 w = Wb[k*144 + g];
                aA = fma2(h1p[k], w.x, aA);
                aB = fma2(h1p[k], w.y, aB);
            }
            a0vp[2*g]   = fma2(di2, aA, a0vp[2*g]);
            a0vp[2*g+1] = fma2(di2, aB, a0vp[2*g+1]);
        }
    }

    // ---- ss pass A: g = 0,1 (cols 0..7), i step 2 — 8 independent chains ----
    u64 a0sp[6];
#pragma unroll
    for (int p = 0; p < 6; p++) a0sp[p] = 0ull;
#pragma unroll 1
    for (int i = 0; i < 24; i += 2) {
        u64 sa = pack2(s[i]);
        u64 sb = pack2(s[i+1]);
        const ulonglong2* Wb = W2 + i*3;
        u64 A0=0ull, B0=0ull, A1=0ull, B1=0ull;
        u64 C0=0ull, D0=0ull, C1=0ull, D1=0ull;
#pragma unroll
        for (int k = 0; k < 16; k++) {
            ulonglong2 w0 = Wb[k*144 + 0];
            ulonglong2 w1 = Wb[k*144 + 1];
            ulonglong2 w2 = Wb[k*144 + 3];
            ulonglong2 w3 = Wb[k*144 + 4];
            A0 = fma2(h1p[k], w0.x, A0);
            B0 = fma2(h1p[k], w0.y, B0);
            A1 = fma2(h1p[k], w1.x, A1);
            B1 = fma2(h1p[k], w1.y, B1);
            C0 = fma2(h1p[k], w2.x, C0);
            D0 = fma2(h1p[k], w2.y, D0);
            C1 = fma2(h1p[k], w3.x, C1);
            D1 = fma2(h1p[k], w3.y, D1);
        }
        a0sp[0] = fma2(sa, A0, a0sp[0]);
        a0sp[1] = fma2(sa, B0, a0sp[1]);
        a0sp[2] = fma2(sa, A1, a0sp[2]);
        a0sp[3] = fma2(sa, B1, a0sp[3]);
        a0sp[0] = fma2(sb, C0, a0sp[0]);
        a0sp[1] = fma2(sb, D0, a0sp[1]);
        a0sp[2] = fma2(sb, C1, a0sp[2]);
        a0sp[3] = fma2(sb, D1, a0sp[3]);
    }

    // ---- ss pass B (g = 2, cols 8..11) fused with sv (chunk 108+i), i step 2 ----
    u64 asvp[2];
    asvp[0] = 0ull; asvp[1] = 0ull;
#pragma unroll 1
    for (int i = 0; i < 24; i += 2) {
        u64 sa = pack2(s[i]);
        u64 sb = pack2(s[i+1]);
        const ulonglong2* Wb = W2 + i*3;
        const ulonglong2* Wv = W2 + 108 + i;
        u64 A0=0ull, B0=0ull, C0=0ull, D0=0ull;
        u64 VA=0ull, VB=0ull, VC=0ull, VD=0ull;
#pragma unroll
        for (int k = 0; k < 16; k++) {
            ulonglong2 w0 = Wb[k*144 + 2];
            ulonglong2 w1 = Wb[k*144 + 5];
            ulonglong2 v0 = Wv[k*144];
            ulonglong2 v1 = Wv[k*144 + 1];
            A0 = fma2(h1p[k], w0.x, A0);
            B0 = fma2(h1p[k], w0.y, B0);
            C0 = fma2(h1p[k], w1.x, C0);
            D0 = fma2(h1p[k], w1.y, D0);
            VA = fma2(h1p[k], v0.x, VA);
            VB = fma2(h1p[k], v0.y, VB);
            VC = fma2(h1p[k], v1.x, VC);
            VD = fma2(h1p[k], v1.y, VD);
        }
        a0sp[4] = fma2(sa, A0, a0sp[4]);
        a0sp[5] = fma2(sa, B0, a0sp[5]);
        a0sp[4] = fma2(sb, C0, a0sp[4]);
        a0sp[5] = fma2(sb, D0, a0sp[5]);
        asvp[0] = fma2(sa, VA, asvp[0]);
        asvp[1] = fma2(sa, VB, asvp[1]);
        asvp[0] = fma2(sb, VC, asvp[0]);
        asvp[1] = fma2(sb, VD, asvp[1]);
    }

    // ---- gating -> g_tmp (scales folded into weights) ----
    float outr[20];
    {
        float a0[12], asv[4], a1[4][3];
#pragma unroll
        for (int p = 0; p < 6; p++) {
            float2 fs = unpack2(a0sp[p]);
            float2 fv = unpack2(a0vp[p]);
            a0[2*p]   = fs.x + fv.x;
            a0[2*p+1] = fs.y + fv.y;
        }
        {
            float2 f0 = unpack2(asvp[0]); float2 f1 = unpack2(asvp[1]);
            asv[0] = f0.x; asv[1] = f0.y; asv[2] = f1.x; asv[3] = f1.y;
        }
#pragma unroll
        for (int c = 0; c < 3; c++) {
            float2 f0 = unpack2(a1p[0][c]); float2 f1 = unpack2(a1p[1][c]);
            a1[0][c] = f0.x; a1[1][c] = f0.y; a1[2][c] = f1.x; a1[3][c] = f1.y;
        }
#pragma unroll
        for (int o = 0; o < 8; o++) outr[o] = fmaxf(a0[o], 0.f);
#pragma unroll
        for (int o = 0; o < 4; o++) {
            float gate = fmaxf(a0[8+o], 0.f);
#pragma unroll
            for (int c = 0; c < 3; c++)
                outr[8 + o*3 + c] = (asv[o]*sh1[c] + a1[o][c]) * gate;
        }
    }
    {
        float4* tp = (float4*)(g_tmp + (size_t)e*20);
        const float4* sp = (const float4*)outr;
#pragma unroll
        for (int t = 0; t < 5; t++) tp[t] = sp[t];
    }
}

// ============================ Kernel B: MLP2 + TP2 + epilogue (fully unrolled) ============================
__global__ __launch_bounds__(128, 4) void edge_tp2_kernel(
    const float* __restrict__ he,
    const int* __restrict__ edst, const float* __restrict__ evec,
    const float* __restrict__ emb, const float* __restrict__ enorm,
    const float* __restrict__ fc2W1, const float* __restrict__ fc2W2,
    float* __restrict__ out_he, int E)
{
    const float SQ3f    = 1.7320508075688772f;
    const float INVSQ3f = 0.57735026918962576f;
    const float RS10    = 0.31622776601683794f;
    const float CS2     = 0.25f;
    const float CV2     = 0.35355339059327379f;

    __shared__ __align__(16) float sW1b[160];
    __shared__ __align__(16) float sW2b[2304];
    {
        const float4* g1b = (const float4*)fc2W1;
        float4* d1b = (float4*)sW1b;
        for (int t = threadIdx.x; t < 40; t += 128) {
            float4 b = g1b[t]; d1b[t] = make_float4(b.x*RS10, b.y*RS10, b.z*RS10, b.w*RS10);
        }
        const float4* g2b = (const float4*)fc2W2;
        float4* d2b = (float4*)sW2b;
        const float sS = CS2 * 0.25f, sV = CV2 * 0.25f;
        for (int t = threadIdx.x; t < 576; t += 128) {
            int c0 = (t*4) % 144;
            float sc = (c0 < 64) ? sS : (c0 < 96) ? sV : (c0 < 128) ? sS : sV;
            float4 a = g2b[t]; d2b[t] = make_float4(a.x*sc, a.y*sc, a.z*sc, a.w*sc);
        }
    }
    __syncthreads();

    int e = blockIdx.x*128 + threadIdx.x;
    if (e >= E) return;

    // load gated intermediates
    float ts[8], tv[12];
    {
        float4 r[5];
        const float4* tp = (const float4*)(g_tmp + (size_t)e*20);
#pragma unroll
        for (int i = 0; i < 5; i++) r[i] = tp[i];
        const float* f = (const float*)r;
#pragma unroll
        for (int j = 0; j < 8; j++) ts[j] = f[j];
#pragma unroll
        for (int j = 0; j < 12; j++) tv[j] = f[8+j];
    }

    float sh1[3];
    {
        float ex = evec[e*3+0], ey = evec[e*3+1], ez = evec[e*3+2];
        float nn = sqrtf(ex*ex + ey*ey + ez*ez) + 1e-12f;
        float f = SQ3f / nn;
        sh1[0] = ex*f; sh1[1] = ey*f; sh1[2] = ez*f;
    }
    float dt[4];
#pragma unroll
    for (int i = 0; i < 4; i++)
        dt[i] = (tv[i*3+0]*sh1[0] + tv[i*3+1]*sh1[1] + tv[i*3+2]*sh1[2]) * INVSQ3f;

    // ---- h2 ----
    u64 h2p[16];
    {
        float embr[10];
        const float2* pe2 = (const float2*)(emb + (size_t)e*10);
#pragma unroll
        for (int j = 0; j < 5; j++) { float2 t = pe2[j]; embr[2*j] = t.x; embr[2*j+1] = t.y; }
        const ulonglong2* W = (const ulonglong2*)sW1b;
        u64 acc[8];
#pragma unroll
        for (int p = 0; p < 8; p++) acc[p] = 0ull;
#pragma unroll
        for (int j = 0; j < 10; j++) {
            u64 ej = pack2(embr[j]);
#pragma unroll
            for (int g = 0; g < 4; g++) {
                ulonglong2 w = W[j*4+g];
                acc[2*g]   = fma2(ej, w.x, acc[2*g]);
                acc[2*g+1] = fma2(ej, w.y, acc[2*g+1]);
            }
        }
#pragma unroll
        for (int p = 0; p < 8; p++) {
            float2 f = unpack2(acc[p]);
            h2p[2*p]   = pack2(fmaxf(f.x, 0.f));
            h2p[2*p+1] = pack2(fmaxf(f.y, 0.f));
        }
    }

    // ---- TP2 (fully unrolled) ----
    const ulonglong2* W2b = (const ulonglong2*)sW2b;  // 36 chunks per k-row
    u64 b0sp[4], b0vp[4], bsvp[2], b1p[2][3];
#pragma unroll
    for (int p = 0; p < 4; p++) { b0sp[p] = 0ull; b0vp[p] = 0ull; }
    bsvp[0] = 0ull; bsvp[1] = 0ull;
#pragma unroll
    for (int c = 0; c < 3; c++) { b1p[0][c] = 0ull; b1p[1][c] = 0ull; }

    // ss: chunk i*2 + g
#pragma unroll
    for (int i = 0; i < 8; i++) {
        u64 si2 = pack2(ts[i]);
#pragma unroll
        for (int g = 0; g < 2; g++) {
            u64 aA = 0ull, aB = 0ull;
#pragma unroll
            for (int k = 0; k < 16; k++) {
                ulonglong2 w = W2b[k*36 + i*2 + g];
                aA = fma2(h2p[k], w.x, aA);
                aB = fma2(h2p[k], w.y, aB);
            }
            b0sp[2*g]   = fma2(si2, aA, b0sp[2*g]);
            b0sp[2*g+1] = fma2(si2, aB, b0sp[2*g+1]);
        }
    }
    // vs: chunk 16 + i*2 + g
#pragma unroll
    for (int i = 0; i < 4; i++) {
        u64 di2 = pack2(dt[i]);
#pragma unroll
        for (int g = 0; g < 2; g++) {
            u64 aA = 0ull, aB = 0ull;
#pragma unroll
            for (int k = 0; k < 16; k++) {
                ulonglong2 w = W2b[k*36 + 16 + i*2 + g];
                aA = fma2(h2p[k], w.x, aA);
                aB = fma2(h2p[k], w.y, aB);
            }
            b0vp[2*g]   = fma2(di2, aA, b0vp[2*g]);
            b0vp[2*g+1] = fma2(di2, aB, b0vp[2*g+1]);
        }
    }
    // sv: chunk 24 + i
#pragma unroll
    for (int i = 0; i < 8; i++) {
        u64 aA = 0ull, aB = 0ull;
#pragma unroll
        for (int k = 0; k < 16; k++) {
            ulonglong2 w = W2b[k*36 + 24 + i];
            aA = fma2(h2p[k], w.x, aA);
            aB = fma2(h2p[k], w.y, aB);
        }
        u64 si2 = pack2(ts[i]);
        bsvp[0] = fma2(si2, aA, bsvp[0]);
        bsvp[1] = fma2(si2, aB, bsvp[1]);
    }
    // vv: chunk 32 + i
#pragma unroll
    for (int i = 0; i < 4; i++) {
        u64 aA = 0ull, aB = 0ull;
#pragma unroll
        for (int k = 0; k < 16; k++) {
            ulonglong2 w = W2b[k*36 + 32 + i];
            aA = fma2(h2p[k], w.x, aA);
            aB = fma2(h2p[k], w.y, aB);
        }
#pragma unroll
        for (int c = 0; c < 3; c++) {
            u64 vc2 = pack2(tv[i*3+c]);
            b1p[0][c] = fma2(vc2, aA, b1p[0][c]);
            b1p[1][c] = fma2(vc2, aB, b1p[1][c]);
        }
    }

    // ---- epilogue (scales folded) ----
    float b0[8], bsv[4], b1[4][3];
#pragma unroll
    for (int p = 0; p < 4; p++) {
        float2 fs = unpack2(b0sp[p]);
        float2 fv = unpack2(b0vp[p]);
        b0[2*p]   = fs.x + fv.x;
        b0[2*p+1] = fs.y + fv.y;
    }
    {
        float2 f0 = unpack2(bsvp[0]); float2 f1 = unpack2(bsvp[1]);
        bsv[0] = f0.x; bsv[1] = f0.y; bsv[2] = f1.x; bsv[3] = f1.y;
    }
#pragma unroll
    for (int c = 0; c < 3; c++) {
        float2 f0 = unpack2(b1p[0][c]); float2 f1 = unpack2(b1p[1][c]);
        b1[0][c] = f0.x; b1[1][c] = f0.y; b1[2][c] = f1.x; b1[3][c] = f1.y;
    }

    float hnew[20];
    {
        float4 r[5];
        const float4* p = (const float4*)(he + (size_t)e*20);
#pragma unroll
        for (int i = 0; i < 5; i++) r[i] = p[i];
        const float* re = (const float*)r;
#pragma unroll
        for (int j = 0; j < 8; j++) hnew[j] = re[j] + b0[j];
#pragma unroll
        for (int o = 0; o < 4; o++)
#pragma unroll
            for (int c = 0; c < 3; c++)
                hnew[8 + o*3 + c] = re[8+o*3+c] + (bsv[o]*sh1[c] + b1[o][c]);
    }

    {
        float4* op = (float4*)(out_he + (size_t)e*20);
        const float4* hp = (const float4*)hnew;
#pragma unroll
        for (int t = 0; t < 5; t++) op[t] = hp[t];
    }
    int dstI = edst[e];
    float nw = enorm[e];
    float* nf = &g_nodeftr[(size_t)dstI*20];
#pragma unroll
    for (int t = 0; t < 5; t++)
        red4(nf + t*4, hnew[t*4]*nw, hnew[t*4+1]*nw, hnew[t*4+2]*nw, hnew[t*4+3]*nw);
}

// ============================ node kernel ============================
__global__ __launch_bounds__(64) void node_kernel(
    const float* __restrict__ hn,
    const float* __restrict__ WgS, const float* __restrict__ WgV,
    const float* __restrict__ WoS, const float* __restrict__ WoV,
    float* __restrict__ out_hn, int N)
{
    const float RS8 = 0.35355339059327379f;
    int n = blockIdx.x*64 + threadIdx.x;
    if (n >= N) return;

    float cs[16], cv[8][3];
    const float* ph = hn + (size_t)n*20;
    const float* pf = g_nodeftr + (size_t)n*20;
#pragma unroll
    for (int j = 0; j < 8; j++) { cs[j] = ph[j]; cs[8+j] = pf[j]; }
#pragma unroll
    for (int i = 0; i < 4; i++)
#pragma unroll
        for (int c = 0; c < 3; c++) { cv[i][c] = ph[8+i*3+c]; cv[4+i][c] = pf[8+i*3+c]; }

    float gl[12];
#pragma unroll
    for (int o = 0; o < 12; o++) {
        float a = 0.f;
#pragma unroll
        for (int i = 0; i < 16; i++) a = fmaf(cs[i], __ldg(&WgS[i*12+o]), a);
        gl[o] = a * 0.25f;
    }
    float vl[4][3];
#pragma unroll
    for (int o = 0; o < 4; o++)
#pragma unroll
        for (int c = 0; c < 3; c++) {
            float a = 0.f;
#pragma unroll
            for (int i = 0; i < 8; i++) a = fmaf(cv[i][c], __ldg(&WgV[i*4+o]), a);
            vl[o][c] = a * RS8;
        }

    float ls[8], lg[4];
#pragma unroll
    for (int j = 0; j < 8; j++) ls[j] = fmaxf(gl[j], 0.f);
#pragma unroll
    for (int o = 0; o < 4; o++) lg[o] = fmaxf(gl[8+o], 0.f);

    float lv[4][3];
#pragma unroll
    for (int o = 0; o < 4; o++)
#pragma unroll
        for (int c = 0; c < 3; c++) lv[o][c] = vl[o][c] * lg[o];

    float os_[8];
#pragma unroll
    for (int o = 0; o < 8; o++) {
        float a = 0.f;
#pragma unroll
        for (int i = 0; i < 8; i++) a = fmaf(ls[i], __ldg(&WoS[i*8+o]), a);
        os_[o] = a * RS8;
    }
    float ov[4][3];
#pragma unroll
    for (int o = 0; o < 4; o++)
#pragma unroll
        for (int c = 0; c < 3; c++) {
            float a = 0.f;
#pragma unroll
            for (int i = 0; i < 4; i++) a = fmaf(lv[i][c], __ldg(&WoV[i*4+o]), a);
            ov[o][c] = a * 0.5f;
        }

    float* po = out_hn + (size_t)n*20;
#pragma unroll
    for (int j = 0; j < 8; j++) po[j] = ph[j] + os_[j];
#pragma unroll
    for (int o = 0; o < 4; o++)
#pragma unroll
        for (int c = 0; c < 3; c++) po[8+o*3+c] = ph[8+o*3+c] + ov[o][c];
}

extern "C" void kernel_launch(void* const* d_in, const int* in_sizes, int n_in,
                              void* d_out, int out_size) {
    const float* hn    = (const float*)d_in[0];
    const float* he    = (const float*)d_in[1];
    const int*   esrc  = (const int*)d_in[2];
    const int*   edst  = (const int*)d_in[3];
    const float* evec  = (const float*)d_in[4];
    const float* emb   = (const float*)d_in[5];
    const float* enorm = (const float*)d_in[6];
    const float* fcW1  = (const float*)d_in[8];
    const float* fcW2  = (const float*)d_in[9];
    const float* fc2W1 = (const float*)d_in[10];
    const float* fc2W2 = (const float*)d_in[11];
    const float* WgS   = (const float*)d_in[12];
    const float* WgV   = (const float*)d_in[13];
    const float* WoS   = (const float*)d_in[14];
    const float* WoV   = (const float*)d_in[15];

    int N = in_sizes[0] / 20;
    int E = in_sizes[1] / 20;

    float* out    = (float*)d_out;
    float* out_hn = out;                      // (N,20) first
    float* out_he = out + (size_t)N * 20;     // (E,20) second

    int n4 = (N * 20) / 4;
    zero_nf_kernel<<<(n4 + 255)/256, 256>>>(n4);
    edge_tp1_kernel<<<(E + 127)/128, 128>>>(hn, he, esrc, edst, evec, emb, fcW1, fcW2, E);
    edge_tp2_kernel<<<(E + 127)/128, 128>>>(he, edst, evec, emb, enorm, fc2W1, fc2W2, out_he, E);
    node_kernel<<<(N + 63)/64, 64>>>(hn, WgS, WgV, WoS, WoV, out_hn, N);
}

// round 8
// speedup vs baseline: 1.2987x; 1.0121x over previous
#include <cuda_runtime.h>

#define NNODES_C 10000
#define NEDGES_C 160000
typedef unsigned long long u64;

__device__ float g_nodeftr[NNODES_C * 20];
__device__ float g_tmp[NEDGES_C * 20];

static __device__ __forceinline__ u64 pack2(float x) {
    u64 r;
    asm("mov.b64 %0, {%1, %1};" : "=l"(r) : "r"(__float_as_uint(x)));
    return r;
}
static __device__ __forceinline__ float2 unpack2(u64 v) {
    float lo, hi;
    asm("mov.b64 {%0, %1}, %2;" : "=f"(lo), "=f"(hi) : "l"(v));
    return make_float2(lo, hi);
}
static __device__ __forceinline__ u64 fma2(u64 a, u64 b, u64 c) {
    u64 d;
    asm("fma.rn.f32x2 %0, %1, %2, %3;" : "=l"(d) : "l"(a), "l"(b), "l"(c));
    return d;
}
static __device__ __forceinline__ void red4(float* p, float a, float b, float c, float d) {
    asm volatile("red.global.add.v4.f32 [%0], {%1, %2, %3, %4};"
                 :: "l"(p), "f"(a), "f"(b), "f"(c), "f"(d) : "memory");
}

__global__ void zero_nf_kernel(int n4) {
    int i = blockIdx.x * blockDim.x + threadIdx.x;
    if (i < n4) ((float4*)g_nodeftr)[i] = make_float4(0.f, 0.f, 0.f, 0.f);
}

// ============================ Kernel A: MLP1 + TP1 + gating ============================
__global__ __launch_bounds__(128, 4) void edge_tp1_kernel(
    const float* __restrict__ hn, const float* __restrict__ he,
    const int* __restrict__ esrc, const int* __restrict__ edst,
    const float* __restrict__ evec, const float* __restrict__ emb,
    const float* __restrict__ fcW1, const float* __restrict__ fcW2, int E)
{
    const float SQ3f    = 1.7320508075688772f;
    const float INVSQ3f = 0.57735026918962576f;
    const float RS10    = 0.31622776601683794f;
    const float CS1     = 0.14433756729740645f;   // 1/sqrt(48)
    const float CV1     = 0.20412414523193150f;   // 1/sqrt(24)

    __shared__ __align__(16) float sW1[160];
    __shared__ __align__(16) float sW2[9216];
    {
        const float4* g1 = (const float4*)fcW1;
        float4* d1 = (float4*)sW1;
        for (int t = threadIdx.x; t < 40; t += 128) {
            float4 a = g1[t]; d1[t] = make_float4(a.x*RS10, a.y*RS10, a.z*RS10, a.w*RS10);
        }
        const float4* g2 = (const float4*)fcW2;
        float4* d2 = (float4*)sW2;
        const float sS = CS1 * 0.25f, sV = CV1 * 0.25f;
        for (int t = threadIdx.x; t < 2304; t += 128) {
            int c0 = (t*4) % 576;
            float sc = (c0 < 288) ? sS : (c0 < 432) ? sV : (c0 < 528) ? sS : sV;
            float4 a = g2[t]; d2[t] = make_float4(a.x*sc, a.y*sc, a.z*sc, a.w*sc);
        }
    }
    __syncthreads();

    int e = blockIdx.x*128 + threadIdx.x;
    if (e >= E) return;

    // ---- gather ----
    int srcI = esrc[e], dstI = edst[e];
    float s[24], vf[36];
    {
        float4 r0[5], r1[5], r2[5];
        const float4* p = (const float4*)(he + (size_t)e*20);
#pragma unroll
        for (int i = 0; i < 5; i++) r0[i] = p[i];
        const float4* ps = (const float4*)(hn + (size_t)srcI*20);
#pragma unroll
        for (int i = 0; i < 5; i++) r1[i] = ps[i];
        const float4* pd = (const float4*)(hn + (size_t)dstI*20);
#pragma unroll
        for (int i = 0; i < 5; i++) r2[i] = pd[i];
        const float* re = (const float*)r0;
        const float* rs = (const float*)r1;
        const float* rd = (const float*)r2;
#pragma unroll
        for (int j = 0; j < 8; j++) { s[j] = re[j]; s[8+j] = rs[j]; s[16+j] = rd[j]; }
#pragma unroll
        for (int j = 0; j < 12; j++) { vf[j] = re[8+j]; vf[12+j] = rs[8+j]; vf[24+j] = rd[8+j]; }
    }

    float sh1[3];
    {
        float ex = evec[e*3+0], ey = evec[e*3+1], ez = evec[e*3+2];
        float nn = sqrtf(ex*ex + ey*ey + ez*ez) + 1e-12f;
        float f = SQ3f / nn;
        sh1[0] = ex*f; sh1[1] = ey*f; sh1[2] = ez*f;
    }
    float dots[12];
#pragma unroll
    for (int i = 0; i < 12; i++)
        dots[i] = (vf[i*3+0]*sh1[0] + vf[i*3+1]*sh1[1] + vf[i*3+2]*sh1[2]) * INVSQ3f;

    // ---- h1 = relu(emb @ fcW1/sqrt(10)) ----
    u64 h1p[16];
    {
        float embr[10];
        const float2* pe2 = (const float2*)(emb + (size_t)e*10);
#pragma unroll
        for (int j = 0; j < 5; j++) { float2 t = pe2[j]; embr[2*j] = t.x; embr[2*j+1] = t.y; }
        const ulonglong2* W = (const ulonglong2*)sW1;
        u64 acc[8];
#pragma unroll
        for (int p = 0; p < 8; p++) acc[p] = 0ull;
#pragma unroll
        for (int j = 0; j < 10; j++) {
            u64 ej = pack2(embr[j]);
#pragma unroll
            for (int g = 0; g < 4; g++) {
                ulonglong2 w = W[j*4+g];
                acc[2*g]   = fma2(ej, w.x, acc[2*g]);
                acc[2*g+1] = fma2(ej, w.y, acc[2*g+1]);
            }
        }
#pragma unroll
        for (int p = 0; p < 8; p++) {
            float2 f = unpack2(acc[p]);
            h1p[2*p]   = pack2(fmaxf(f.x, 0.f));
            h1p[2*p+1] = pack2(fmaxf(f.y, 0.f));
        }
    }

    const ulonglong2* W2 = (const ulonglong2*)sW2;   // 144 chunks per k-row

    // ---- vv: chunk 132 + i  (unrolled; consumes vf, then vf dead) ----
    u64 a1p[2][3];
#pragma unroll
    for (int c = 0; c < 3; c++) { a1p[0][c] = 0ull; a1p[1][c] = 0ull; }
#pragma unroll
    for (int i = 0; i < 12; i++) {
        u64 aA = 0ull, aB = 0ull;
#pragma unroll
        for (int k = 0; k < 16; k++) {
            ulonglong2 w = W2[k*144 + 132 + i];
            aA = fma2(h1p[k], w.x, aA);
            aB = fma2(h1p[k], w.y, aB);
        }
#pragma unroll
        for (int c = 0; c < 3; c++) {
            u64 vc2 = pack2(vf[i*3+c]);
            a1p[0][c] = fma2(vc2, aA, a1p[0][c]);
            a1p[1][c] = fma2(vc2, aB, a1p[1][c]);
        }
    }

    // shared accumulators for out0: vs accumulates first, ss adds on top
    u64 a0p[6];
#pragma unroll
    for (int p = 0; p < 6; p++) a0p[p] = 0ull;

    // ---- vs: chunk 72 + i*3 + g  (rolled; consumes dots, then dots dead) ----
#pragma unroll 1
    for (int i = 0; i < 12; i += 2) {
        u64 da = pack2(dots[i]);
        u64 db = pack2(dots[i+1]);
        const ulonglong2* Wb = W2 + 72 + i*3;
#pragma unroll
        for (int g = 0; g < 3; g++) {
            u64 aA = 0ull, aB = 0ull, bA = 0ull, bB = 0ull;
#pragma unroll
            for (int k = 0; k < 16; k++) {
                ulonglong2 wa = Wb[k*144 + g];
                ulonglong2 wb = Wb[k*144 + 3 + g];
                aA = fma2(h1p[k], wa.x, aA);
                aB = fma2(h1p[k], wa.y, aB);
                bA = fma2(h1p[k], wb.x, bA);
                bB = fma2(h1p[k], wb.y, bB);
            }
            a0p[2*g]   = fma2(da, aA, a0p[2*g]);
            a0p[2*g+1] = fma2(da, aB, a0p[2*g+1]);
            a0p[2*g]   = fma2(db, bA, a0p[2*g]);
            a0p[2*g+1] = fma2(db, bB, a0p[2*g+1]);
        }
    }

    // ---- ss pass A: g = 0,1 (cols 0..7), i step 2 — 8 independent chains ----
#pragma unroll 1
    for (int i = 0; i < 24; i += 2) {
        u64 sa = pack2(s[i]);
        u64 sb = pack2(s[i+1]);
        const ulonglong2* Wb = W2 + i*3;
        u64 A0=0ull, B0=0ull, A1=0ull, B1=0ull;
        u64 C0=0ull, D0=0ull, C1=0ull, D1=0ull;
#pragma unroll
        for (int k = 0; k < 16; k++) {
            ulonglong2 w0 = Wb[k*144 + 0];
            ulonglong2 w1 = Wb[k*144 + 1];
            ulonglong2 w2 = Wb[k*144 + 3];
            ulonglong2 w3 = Wb[k*144 + 4];
            A0 = fma2(h1p[k], w0.x, A0);
            B0 = fma2(h1p[k], w0.y, B0);
            A1 = fma2(h1p[k], w1.x, A1);
            B1 = fma2(h1p[k], w1.y, B1);
            C0 = fma2(h1p[k], w2.x, C0);
            D0 = fma2(h1p[k], w2.y, D0);
            C1 = fma2(h1p[k], w3.x, C1);
            D1 = fma2(h1p[k], w3.y, D1);
        }
        a0p[0] = fma2(sa, A0, a0p[0]);
        a0p[1] = fma2(sa, B0, a0p[1]);
        a0p[2] = fma2(sa, A1, a0p[2]);
        a0p[3] = fma2(sa, B1, a0p[3]);
        a0p[0] = fma2(sb, C0, a0p[0]);
        a0p[1] = fma2(sb, D0, a0p[1]);
        a0p[2] = fma2(sb, C1, a0p[2]);
        a0p[3] = fma2(sb, D1, a0p[3]);
    }

    // ---- ss pass B (g = 2, cols 8..11) fused with sv (chunk 108+i), i step 2 ----
    u64 asvp[2];
    asvp[0] = 0ull; asvp[1] = 0ull;
#pragma unroll 1
    for (int i = 0; i < 24; i += 2) {
        u64 sa = pack2(s[i]);
        u64 sb = pack2(s[i+1]);
        const ulonglong2* Wb = W2 + i*3;
        const ulonglong2* Wv = W2 + 108 + i;
        u64 A0=0ull, B0=0ull, C0=0ull, D0=0ull;
        u64 VA=0ull, VB=0ull, VC=0ull, VD=0ull;
#pragma unroll
        for (int k = 0; k < 16; k++) {
            ulonglong2 w0 = Wb[k*144 + 2];
            ulonglong2 w1 = Wb[k*144 + 5];
            ulonglong2 v0 = Wv[k*144];
            ulonglong2 v1 = Wv[k*144 + 1];
            A0 = fma2(h1p[k], w0.x, A0);
            B0 = fma2(h1p[k], w0.y, B0);
            C0 = fma2(h1p[k], w1.x, C0);
            D0 = fma2(h1p[k], w1.y, D0);
            VA = fma2(h1p[k], v0.x, VA);
            VB = fma2(h1p[k], v0.y, VB);
            VC = fma2(h1p[k], v1.x, VC);
            VD = fma2(h1p[k], v1.y, VD);
        }
        a0p[4] = fma2(sa, A0, a0p[4]);
        a0p[5] = fma2(sa, B0, a0p[5]);
        a0p[4] = fma2(sb, C0, a0p[4]);
        a0p[5] = fma2(sb, D0, a0p[5]);
        asvp[0] = fma2(sa, VA, asvp[0]);
        asvp[1] = fma2(sa, VB, asvp[1]);
        asvp[0] = fma2(sb, VC, asvp[0]);
        asvp[1] = fma2(sb, VD, asvp[1]);
    }

    // ---- gating -> g_tmp (scales folded into weights) ----
    float outr[20];
    {
        float a0[12], asv[4], a1[4][3];
#pragma unroll
        for (int p = 0; p < 6; p++) {
            float2 f = unpack2(a0p[p]);
            a0[2*p] = f.x; a0[2*p+1] = f.y;
        }
        {
            float2 f0 = unpack2(asvp[0]); float2 f1 = unpack2(asvp[1]);
            asv[0] = f0.x; asv[1] = f0.y; asv[2] = f1.x; asv[3] = f1.y;
        }
#pragma unroll
        for (int c = 0; c < 3; c++) {
            float2 f0 = unpack2(a1p[0][c]); float2 f1 = unpack2(a1p[1][c]);
            a1[0][c] = f0.x; a1[1][c] = f0.y; a1[2][c] = f1.x; a1[3][c] = f1.y;
        }
#pragma unroll
        for (int o = 0; o < 8; o++) outr[o] = fmaxf(a0[o], 0.f);
#pragma unroll
        for (int o = 0; o < 4; o++) {
            float gate = fmaxf(a0[8+o], 0.f);
#pragma unroll
            for (int c = 0; c < 3; c++)
                outr[8 + o*3 + c] = (asv[o]*sh1[c] + a1[o][c]) * gate;
        }
    }
    {
        float4* tp = (float4*)(g_tmp + (size_t)e*20);
        const float4* sp = (const float4*)outr;
#pragma unroll
        for (int t = 0; t < 5; t++) tp[t] = sp[t];
    }
}

// ============================ Kernel B: MLP2 + TP2 + epilogue (fully unrolled) ============================
__global__ __launch_bounds__(128, 4) void edge_tp2_kernel(
    const float* __restrict__ he,
    const int* __restrict__ edst, const float* __restrict__ evec,
    const float* __restrict__ emb, const float* __restrict__ enorm,
    const float* __restrict__ fc2W1, const float* __restrict__ fc2W2,
    float* __restrict__ out_he, int E)
{
    const float SQ3f    = 1.7320508075688772f;
    const float INVSQ3f = 0.57735026918962576f;
    const float RS10    = 0.31622776601683794f;
    const float CS2     = 0.25f;
    const float CV2     = 0.35355339059327379f;

    __shared__ __align__(16) float sW1b[160];
    __shared__ __align__(16) float sW2b[2304];
    {
        const float4* g1b = (const float4*)fc2W1;
        float4* d1b = (float4*)sW1b;
        for (int t = threadIdx.x; t < 40; t += 128) {
            float4 b = g1b[t]; d1b[t] = make_float4(b.x*RS10, b.y*RS10, b.z*RS10, b.w*RS10);
        }
        const float4* g2b = (const float4*)fc2W2;
        float4* d2b = (float4*)sW2b;
        const float sS = CS2 * 0.25f, sV = CV2 * 0.25f;
        for (int t = threadIdx.x; t < 576; t += 128) {
            int c0 = (t*4) % 144;
            float sc = (c0 < 64) ? sS : (c0 < 96) ? sV : (c0 < 128) ? sS : sV;
            float4 a = g2b[t]; d2b[t] = make_float4(a.x*sc, a.y*sc, a.z*sc, a.w*sc);
        }
    }
    __syncthreads();

    int e = blockIdx.x*128 + threadIdx.x;
    if (e >= E) return;

    // load gated intermediates
    float ts[8], tv[12];
    {
        float4 r[5];
        const float4* tp = (const float4*)(g_tmp + (size_t)e*20);
#pragma unroll
        for (int i = 0; i < 5; i++) r[i] = tp[i];
        const float* f = (const float*)r;
#pragma unroll
        for (int j = 0; j < 8; j++) ts[j] = f[j];
#pragma unroll
        for (int j = 0; j < 12; j++) tv[j] = f[8+j];
    }

    float sh1[3];
    {
        float ex = evec[e*3+0], ey = evec[e*3+1], ez = evec[e*3+2];
        float nn = sqrtf(ex*ex + ey*ey + ez*ez) + 1e-12f;
        float f = SQ3f / nn;
        sh1[0] = ex*f; sh1[1] = ey*f; sh1[2] = ez*f;
    }
    float dt[4];
#pragma unroll
    for (int i = 0; i < 4; i++)
        dt[i] = (tv[i*3+0]*sh1[0] + tv[i*3+1]*sh1[1] + tv[i*3+2]*sh1[2]) * INVSQ3f;

    // ---- h2 ----
    u64 h2p[16];
    {
        float embr[10];
        const float2* pe2 = (const float2*)(emb + (size_t)e*10);
#pragma unroll
        for (int j = 0; j < 5; j++) { float2 t = pe2[j]; embr[2*j] = t.x; embr[2*j+1] = t.y; }
        const ulonglong2* W = (const ulonglong2*)sW1b;
        u64 acc[8];
#pragma unroll
        for (int p = 0; p < 8; p++) acc[p] = 0ull;
#pragma unroll
        for (int j = 0; j < 10; j++) {
            u64 ej = pack2(embr[j]);
#pragma unroll
            for (int g = 0; g < 4; g++) {
                ulonglong2 w = W[j*4+g];
                acc[2*g]   = fma2(ej, w.x, acc[2*g]);
                acc[2*g+1] = fma2(ej, w.y, acc[2*g+1]);
            }
        }
#pragma unroll
        for (int p = 0; p < 8; p++) {
            float2 f = unpack2(acc[p]);
            h2p[2*p]   = pack2(fmaxf(f.x, 0.f));
            h2p[2*p+1] = pack2(fmaxf(f.y, 0.f));
        }
    }

    // ---- TP2 (fully unrolled), shared out0 accumulators ----
    const ulonglong2* W2b = (const ulonglong2*)sW2b;  // 36 chunks per k-row
    u64 b0p[4], bsvp[2], b1p[2][3];
#pragma unroll
    for (int p = 0; p < 4; p++) b0p[p] = 0ull;
    bsvp[0] = 0ull; bsvp[1] = 0ull;
#pragma unroll
    for (int c = 0; c < 3; c++) { b1p[0][c] = 0ull; b1p[1][c] = 0ull; }

    // ss: chunk i*2 + g
#pragma unroll
    for (int i = 0; i < 8; i++) {
        u64 si2 = pack2(ts[i]);
#pragma unroll
        for (int g = 0; g < 2; g++) {
            u64 aA = 0ull, aB = 0ull;
#pragma unroll
            for (int k = 0; k < 16; k++) {
                ulonglong2 w = W2b[k*36 + i*2 + g];
                aA = fma2(h2p[k], w.x, aA);
                aB = fma2(h2p[k], w.y, aB);
            }
            b0p[2*g]   = fma2(si2, aA, b0p[2*g]);
            b0p[2*g+1] = fma2(si2, aB, b0p[2*g+1]);
        }
    }
    // vs: chunk 16 + i*2 + g (accumulates into b0p)
#pragma unroll
    for (int i = 0; i < 4; i++) {
        u64 di2 = pack2(dt[i]);
#pragma unroll
        for (int g = 0; g < 2; g++) {
            u64 aA = 0ull, aB = 0ull;
#pragma unroll
            for (int k = 0; k < 16; k++) {
                ulonglong2 w = W2b[k*36 + 16 + i*2 + g];
                aA = fma2(h2p[k], w.x, aA);
                aB = fma2(h2p[k], w.y, aB);
            }
            b0p[2*g]   = fma2(di2, aA, b0p[2*g]);
            b0p[2*g+1] = fma2(di2, aB, b0p[2*g+1]);
        }
    }
    // sv: chunk 24 + i
#pragma unroll
    for (int i = 0; i < 8; i++) {
        u64 aA = 0ull, aB = 0ull;
#pragma unroll
        for (int k = 0; k < 16; k++) {
            ulonglong2 w = W2b[k*36 + 24 + i];
            aA = fma2(h2p[k], w.x, aA);
            aB = fma2(h2p[k], w.y, aB);
        }
        u64 si2 = pack2(ts[i]);
        bsvp[0] = fma2(si2, aA, bsvp[0]);
        bsvp[1] = fma2(si2, aB, bsvp[1]);
    }
    // vv: chunk 32 + i
#pragma unroll
    for (int i = 0; i < 4; i++) {
        u64 aA = 0ull, aB = 0ull;
#pragma unroll
        for (int k = 0; k < 16; k++) {
            ulonglong2 w = W2b[k*36 + 32 + i];
            aA = fma2(h2p[k], w.x, aA);
            aB = fma2(h2p[k], w.y, aB);
        }
#pragma unroll
        for (int c = 0; c < 3; c++) {
            u64 vc2 = pack2(tv[i*3+c]);
            b1p[0][c] = fma2(vc2, aA, b1p[0][c]);
            b1p[1][c] = fma2(vc2, aB, b1p[1][c]);
        }
    }

    // ---- epilogue (scales folded) ----
    float b0[8], bsv[4], b1[4][3];
#pragma unroll
    for (int p = 0; p < 4; p++) {
        float2 f = unpack2(b0p[p]);
        b0[2*p] = f.x; b0[2*p+1] = f.y;
    }
    {
        float2 f0 = unpack2(bsvp[0]); float2 f1 = unpack2(bsvp[1]);
        bsv[0] = f0.x; bsv[1] = f0.y; bsv[2] = f1.x; bsv[3] = f1.y;
    }
#pragma unroll
    for (int c = 0; c < 3; c++) {
        float2 f0 = unpack2(b1p[0][c]); float2 f1 = unpack2(b1p[1][c]);
        b1[0][c] = f0.x; b1[1][c] = f0.y; b1[2][c] = f1.x; b1[3][c] = f1.y;
    }

    float hnew[20];
    {
        float4 r[5];
        const float4* p = (const float4*)(he + (size_t)e*20);
#pragma unroll
        for (int i = 0; i < 5; i++) r[i] = p[i];
        const float* re = (const float*)r;
#pragma unroll
        for (int j = 0; j < 8; j++) hnew[j] = re[j] + b0[j];
#pragma unroll
        for (int o = 0; o < 4; o++)
#pragma unroll
            for (int c = 0; c < 3; c++)
                hnew[8 + o*3 + c] = re[8+o*3+c] + (bsv[o]*sh1[c] + b1[o][c]);
    }

    {
        float4* op = (float4*)(out_he + (size_t)e*20);
        const float4* hp = (const float4*)hnew;
#pragma unroll
        for (int t = 0; t < 5; t++) op[t] = hp[t];
    }
    int dstI = edst[e];
    float nw = enorm[e];
    float* nf = &g_nodeftr[(size_t)dstI*20];
#pragma unroll
    for (int t = 0; t < 5; t++)
        red4(nf + t*4, hnew[t*4]*nw, hnew[t*4+1]*nw, hnew[t*4+2]*nw, hnew[t*4+3]*nw);
}

// ============================ node kernel ============================
__global__ __launch_bounds__(64) void node_kernel(
    const float* __restrict__ hn,
    const float* __restrict__ WgS, const float* __restrict__ WgV,
    const float* __restrict__ WoS, const float* __restrict__ WoV,
    float* __restrict__ out_hn, int N)
{
    const float RS8 = 0.35355339059327379f;
    int n = blockIdx.x*64 + threadIdx.x;
    if (n >= N) return;

    float cs[16], cv[8][3];
    const float* ph = hn + (size_t)n*20;
    const float* pf = g_nodeftr + (size_t)n*20;
#pragma unroll
    for (int j = 0; j < 8; j++) { cs[j] = ph[j]; cs[8+j] = pf[j]; }
#pragma unroll
    for (int i = 0; i < 4; i++)
#pragma unroll
        for (int c = 0; c < 3; c++) { cv[i][c] = ph[8+i*3+c]; cv[4+i][c] = pf[8+i*3+c]; }

    float gl[12];
#pragma unroll
    for (int o = 0; o < 12; o++) {
        float a = 0.f;
#pragma unroll
        for (int i = 0; i < 16; i++) a = fmaf(cs[i], __ldg(&WgS[i*12+o]), a);
        gl[o] = a * 0.25f;
    }
    float vl[4][3];
#pragma unroll
    for (int o = 0; o < 4; o++)
#pragma unroll
        for (int c = 0; c < 3; c++) {
            float a = 0.f;
#pragma unroll
            for (int i = 0; i < 8; i++) a = fmaf(cv[i][c], __ldg(&WgV[i*4+o]), a);
            vl[o][c] = a * RS8;
        }

    float ls[8], lg[4];
#pragma unroll
    for (int j = 0; j < 8; j++) ls[j] = fmaxf(gl[j], 0.f);
#pragma unroll
    for (int o = 0; o < 4; o++) lg[o] = fmaxf(gl[8+o], 0.f);

    float lv[4][3];
#pragma unroll
    for (int o = 0; o < 4; o++)
#pragma unroll
        for (int c = 0; c < 3; c++) lv[o][c] = vl[o][c] * lg[o];

    float os_[8];
#pragma unroll
    for (int o = 0; o < 8; o++) {
        float a = 0.f;
#pragma unroll
        for (int i = 0; i < 8; i++) a = fmaf(ls[i], __ldg(&WoS[i*8+o]), a);
        os_[o] = a * RS8;
    }
    float ov[4][3];
#pragma unroll
    for (int o = 0; o < 4; o++)
#pragma unroll
        for (int c = 0; c < 3; c++) {
            float a = 0.f;
#pragma unroll
            for (int i = 0; i < 4; i++) a = fmaf(lv[i][c], __ldg(&WoV[i*4+o]), a);
            ov[o][c] = a * 0.5f;
        }

    float* po = out_hn + (size_t)n*20;
#pragma unroll
    for (int j = 0; j < 8; j++) po[j] = ph[j] + os_[j];
#pragma unroll
    for (int o = 0; o < 4; o++)
#pragma unroll
        for (int c = 0; c < 3; c++) po[8+o*3+c] = ph[8+o*3+c] + ov[o][c];
}

extern "C" void kernel_launch(void* const* d_in, const int* in_sizes, int n_in,
                              void* d_out, int out_size) {
    const float* hn    = (const float*)d_in[0];
    const float* he    = (const float*)d_in[1];
    const int*   esrc  = (const int*)d_in[2];
    const int*   edst  = (const int*)d_in[3];
    const float* evec  = (const float*)d_in[4];
    const float* emb   = (const float*)d_in[5];
    const float* enorm = (const float*)d_in[6];
    const float* fcW1  = (const float*)d_in[8];
    const float* fcW2  = (const float*)d_in[9];
    const float* fc2W1 = (const float*)d_in[10];
    const float* fc2W2 = (const float*)d_in[11];
    const float* WgS   = (const float*)d_in[12];
    const float* WgV   = (const float*)d_in[13];
    const float* WoS   = (const float*)d_in[14];
    const float* WoV   = (const float*)d_in[15];

    int N = in_sizes[0] / 20;
    int E = in_sizes[1] / 20;

    float* out    = (float*)d_out;
    float* out_hn = out;                      // (N,20) first
    float* out_he = out + (size_t)N * 20;     // (E,20) second

    int n4 = (N * 20) / 4;
    zero_nf_kernel<<<(n4 + 255)/256, 256>>>(n4);
    edge_tp1_kernel<<<(E + 127)/128, 128>>>(hn, he, esrc, edst, evec, emb, fcW1, fcW2, E);
    edge_tp2_kernel<<<(E + 127)/128, 128>>>(he, edst, evec, emb, enorm, fc2W1, fc2W2, out_he, E);
    node_kernel<<<(N + 63)/64, 64>>>(hn, WgS, WgV, WoS, WoV, out_hn, N);
}

// round 9
// speedup vs baseline: 1.2990x; 1.0002x over previous
#include <cuda_runtime.h>

#define NNODES_C 10000
#define NEDGES_C 160000
typedef unsigned long long u64;

__device__ float g_nodeftr[NNODES_C * 20];   // zero-initialized at load; node_kernel re-zeroes after use
__device__ float g_tmp[NEDGES_C * 20];

static __device__ __forceinline__ u64 pack2(float x) {
    u64 r;
    asm("mov.b64 %0, {%1, %1};" : "=l"(r) : "r"(__float_as_uint(x)));
    return r;
}
static __device__ __forceinline__ float2 unpack2(u64 v) {
    float lo, hi;
    asm("mov.b64 {%0, %1}, %2;" : "=f"(lo), "=f"(hi) : "l"(v));
    return make_float2(lo, hi);
}
static __device__ __forceinline__ u64 fma2(u64 a, u64 b, u64 c) {
    u64 d;
    asm("fma.rn.f32x2 %0, %1, %2, %3;" : "=l"(d) : "l"(a), "l"(b), "l"(c));
    return d;
}
static __device__ __forceinline__ void red4(float* p, float a, float b, float c, float d) {
    asm volatile("red.global.add.v4.f32 [%0], {%1, %2, %3, %4};"
                 :: "l"(p), "f"(a), "f"(b), "f"(c), "f"(d) : "memory");
}

// ============================ Kernel A: MLP1 + TP1 + gating ============================
__global__ __launch_bounds__(128, 4) void edge_tp1_kernel(
    const float* __restrict__ hn, const float* __restrict__ he,
    const int* __restrict__ esrc, const int* __restrict__ edst,
    const float* __restrict__ evec, const float* __restrict__ emb,
    const float* __restrict__ fcW1, const float* __restrict__ fcW2, int E)
{
    const float SQ3f    = 1.7320508075688772f;
    const float INVSQ3f = 0.57735026918962576f;
    const float RS10    = 0.31622776601683794f;
    const float CS1     = 0.14433756729740645f;   // 1/sqrt(48)
    const float CV1     = 0.20412414523193150f;   // 1/sqrt(24)

    __shared__ __align__(16) float sW1[160];
    __shared__ __align__(16) float sW2[9216];
    {
        const float4* g1 = (const float4*)fcW1;
        float4* d1 = (float4*)sW1;
        for (int t = threadIdx.x; t < 40; t += 128) {
            float4 a = g1[t]; d1[t] = make_float4(a.x*RS10, a.y*RS10, a.z*RS10, a.w*RS10);
        }
        const float4* g2 = (const float4*)fcW2;
        float4* d2 = (float4*)sW2;
        const float sS = CS1 * 0.25f, sV = CV1 * 0.25f;
        for (int t = threadIdx.x; t < 2304; t += 128) {
            int c0 = (t*4) % 576;
            float sc = (c0 < 288) ? sS : (c0 < 432) ? sV : (c0 < 528) ? sS : sV;
            float4 a = g2[t]; d2[t] = make_float4(a.x*sc, a.y*sc, a.z*sc, a.w*sc);
        }
    }
    __syncthreads();

    int e = blockIdx.x*128 + threadIdx.x;
    if (e >= E) return;

    // ---- gather ----
    int srcI = esrc[e], dstI = edst[e];
    float s[24], vf[36];
    {
        float4 r0[5], r1[5], r2[5];
        const float4* p = (const float4*)(he + (size_t)e*20);
#pragma unroll
        for (int i = 0; i < 5; i++) r0[i] = p[i];
        const float4* ps = (const float4*)(hn + (size_t)srcI*20);
#pragma unroll
        for (int i = 0; i < 5; i++) r1[i] = ps[i];
        const float4* pd = (const float4*)(hn + (size_t)dstI*20);
#pragma unroll
        for (int i = 0; i < 5; i++) r2[i] = pd[i];
        const float* re = (const float*)r0;
        const float* rs = (const float*)r1;
        const float* rd = (const float*)r2;
#pragma unroll
        for (int j = 0; j < 8; j++) { s[j] = re[j]; s[8+j] = rs[j]; s[16+j] = rd[j]; }
#pragma unroll
        for (int j = 0; j < 12; j++) { vf[j] = re[8+j]; vf[12+j] = rs[8+j]; vf[24+j] = rd[8+j]; }
    }

    float sh1[3];
    {
        float ex = evec[e*3+0], ey = evec[e*3+1], ez = evec[e*3+2];
        float nn = sqrtf(ex*ex + ey*ey + ez*ez) + 1e-12f;
        float f = SQ3f / nn;
        sh1[0] = ex*f; sh1[1] = ey*f; sh1[2] = ez*f;
    }
    float dots[12];
#pragma unroll
    for (int i = 0; i < 12; i++)
        dots[i] = (vf[i*3+0]*sh1[0] + vf[i*3+1]*sh1[1] + vf[i*3+2]*sh1[2]) * INVSQ3f;

    // ---- h1 = relu(emb @ fcW1/sqrt(10)) ----
    u64 h1p[16];
    {
        float embr[10];
        const float2* pe2 = (const float2*)(emb + (size_t)e*10);
#pragma unroll
        for (int j = 0; j < 5; j++) { float2 t = pe2[j]; embr[2*j] = t.x; embr[2*j+1] = t.y; }
        const ulonglong2* W = (const ulonglong2*)sW1;
        u64 acc[8];
#pragma unroll
        for (int p = 0; p < 8; p++) acc[p] = 0ull;
#pragma unroll
        for (int j = 0; j < 10; j++) {
            u64 ej = pack2(embr[j]);
#pragma unroll
            for (int g = 0; g < 4; g++) {
                ulonglong2 w = W[j*4+g];
                acc[2*g]   = fma2(ej, w.x, acc[2*g]);
                acc[2*g+1] = fma2(ej, w.y, acc[2*g+1]);
            }
        }
#pragma unroll
        for (int p = 0; p < 8; p++) {
            float2 f = unpack2(acc[p]);
            h1p[2*p]   = pack2(fmaxf(f.x, 0.f));
            h1p[2*p+1] = pack2(fmaxf(f.y, 0.f));
        }
    }

    const ulonglong2* W2 = (const ulonglong2*)sW2;   // 144 chunks per k-row

    // ---- vv: chunk 132 + i  (unrolled; consumes vf, then vf dead) ----
    u64 a1p[2][3];
#pragma unroll
    for (int c = 0; c < 3; c++) { a1p[0][c] = 0ull; a1p[1][c] = 0ull; }
#pragma unroll
    for (int i = 0; i < 12; i++) {
        u64 aA = 0ull, aB = 0ull;
#pragma unroll
        for (int k = 0; k < 16; k++) {
            ulonglong2 w = W2[k*144 + 132 + i];
            aA = fma2(h1p[k], w.x, aA);
            aB = fma2(h1p[k], w.y, aB);
        }
#pragma unroll
        for (int c = 0; c < 3; c++) {
            u64 vc2 = pack2(vf[i*3+c]);
            a1p[0][c] = fma2(vc2, aA, a1p[0][c]);
            a1p[1][c] = fma2(vc2, aB, a1p[1][c]);
        }
    }

    // shared accumulators for out0: vs accumulates first, ss adds on top
    u64 a0p[6];
#pragma unroll
    for (int p = 0; p < 6; p++) a0p[p] = 0ull;

    // ---- vs: chunk 72 + i*3 + g  (rolled; consumes dots, then dots dead) ----
#pragma unroll 1
    for (int i = 0; i < 12; i += 2) {
        u64 da = pack2(dots[i]);
        u64 db = pack2(dots[i+1]);
        const ulonglong2* Wb = W2 + 72 + i*3;
#pragma unroll
        for (int g = 0; g < 3; g++) {
            u64 aA = 0ull, aB = 0ull, bA = 0ull, bB = 0ull;
#pragma unroll
            for (int k = 0; k < 16; k++) {
                ulonglong2 wa = Wb[k*144 + g];
                ulonglong2 wb = Wb[k*144 + 3 + g];
                aA = fma2(h1p[k], wa.x, aA);
                aB = fma2(h1p[k], wa.y, aB);
                bA = fma2(h1p[k], wb.x, bA);
                bB = fma2(h1p[k], wb.y, bB);
            }
            a0p[2*g]   = fma2(da, aA, a0p[2*g]);
            a0p[2*g+1] = fma2(da, aB, a0p[2*g+1]);
            a0p[2*g]   = fma2(db, bA, a0p[2*g]);
            a0p[2*g+1] = fma2(db, bB, a0p[2*g+1]);
        }
    }

    // ---- ss pass A: g = 0,1 (cols 0..7), i step 2 — 8 independent chains ----
#pragma unroll 1
    for (int i = 0; i < 24; i += 2) {
        u64 sa = pack2(s[i]);
        u64 sb = pack2(s[i+1]);
        const ulonglong2* Wb = W2 + i*3;
        u64 A0=0ull, B0=0ull, A1=0ull, B1=0ull;
        u64 C0=0ull, D0=0ull, C1=0ull, D1=0ull;
#pragma unroll
        for (int k = 0; k < 16; k++) {
            ulonglong2 w0 = Wb[k*144 + 0];
            ulonglong2 w1 = Wb[k*144 + 1];
            ulonglong2 w2 = Wb[k*144 + 3];
            ulonglong2 w3 = Wb[k*144 + 4];
            A0 = fma2(h1p[k], w0.x, A0);
            B0 = fma2(h1p[k], w0.y, B0);
            A1 = fma2(h1p[k], w1.x, A1);
            B1 = fma2(h1p[k], w1.y, B1);
            C0 = fma2(h1p[k], w2.x, C0);
            D0 = fma2(h1p[k], w2.y, D0);
            C1 = fma2(h1p[k], w3.x, C1);
            D1 = fma2(h1p[k], w3.y, D1);
        }
        a0p[0] = fma2(sa, A0, a0p[0]);
        a0p[1] = fma2(sa, B0, a0p[1]);
        a0p[2] = fma2(sa, A1, a0p[2]);
        a0p[3] = fma2(sa, B1, a0p[3]);
        a0p[0] = fma2(sb, C0, a0p[0]);
        a0p[1] = fma2(sb, D0, a0p[1]);
        a0p[2] = fma2(sb, C1, a0p[2]);
        a0p[3] = fma2(sb, D1, a0p[3]);
    }

    // ---- ss pass B (g = 2, cols 8..11) fused with sv (chunk 108+i), i step 2 ----
    u64 asvp[2];
    asvp[0] = 0ull; asvp[1] = 0ull;
#pragma unroll 1
    for (int i = 0; i < 24; i += 2) {
        u64 sa = pack2(s[i]);
        u64 sb = pack2(s[i+1]);
        const ulonglong2* Wb = W2 + i*3;
        const ulonglong2* Wv = W2 + 108 + i;
        u64 A0=0ull, B0=0ull, C0=0ull, D0=0ull;
        u64 VA=0ull, VB=0ull, VC=0ull, VD=0ull;
#pragma unroll
        for (int k = 0; k < 16; k++) {
            ulonglong2 w0 = Wb[k*144 + 2];
            ulonglong2 w1 = Wb[k*144 + 5];
            ulonglong2 v0 = Wv[k*144];
            ulonglong2 v1 = Wv[k*144 + 1];
            A0 = fma2(h1p[k], w0.x, A0);
            B0 = fma2(h1p[k], w0.y, B0);
            C0 = fma2(h1p[k], w1.x, C0);
            D0 = fma2(h1p[k], w1.y, D0);
            VA = fma2(h1p[k], v0.x, VA);
            VB = fma2(h1p[k], v0.y, VB);
            VC = fma2(h1p[k], v1.x, VC);
            VD = fma2(h1p[k], v1.y, VD);
        }
        a0p[4] = fma2(sa, A0, a0p[4]);
        a0p[5] = fma2(sa, B0, a0p[5]);
        a0p[4] = fma2(sb, C0, a0p[4]);
        a0p[5] = fma2(sb, D0, a0p[5]);
        asvp[0] = fma2(sa, VA, asvp[0]);
        asvp[1] = fma2(sa, VB, asvp[1]);
        asvp[0] = fma2(sb, VC, asvp[0]);
        asvp[1] = fma2(sb, VD, asvp[1]);
    }

    // ---- gating -> g_tmp (scales folded into weights) ----
    float outr[20];
    {
        float a0[12], asv[4], a1[4][3];
#pragma unroll
        for (int p = 0; p < 6; p++) {
            float2 f = unpack2(a0p[p]);
            a0[2*p] = f.x; a0[2*p+1] = f.y;
        }
        {
            float2 f0 = unpack2(asvp[0]); float2 f1 = unpack2(asvp[1]);
            asv[0] = f0.x; asv[1] = f0.y; asv[2] = f1.x; asv[3] = f1.y;
        }
#pragma unroll
        for (int c = 0; c < 3; c++) {
            float2 f0 = unpack2(a1p[0][c]); float2 f1 = unpack2(a1p[1][c]);
            a1[0][c] = f0.x; a1[1][c] = f0.y; a1[2][c] = f1.x; a1[3][c] = f1.y;
        }
#pragma unroll
        for (int o = 0; o < 8; o++) outr[o] = fmaxf(a0[o], 0.f);
#pragma unroll
        for (int o = 0; o < 4; o++) {
            float gate = fmaxf(a0[8+o], 0.f);
#pragma unroll
            for (int c = 0; c < 3; c++)
                outr[8 + o*3 + c] = (asv[o]*sh1[c] + a1[o][c]) * gate;
        }
    }
    {
        float4* tp = (float4*)(g_tmp + (size_t)e*20);
        const float4* sp = (const float4*)outr;
#pragma unroll
        for (int t = 0; t < 5; t++) tp[t] = sp[t];
    }
}

// ============================ Kernel B: MLP2 + TP2 + epilogue (fully unrolled) ============================
__global__ __launch_bounds__(128, 4) void edge_tp2_kernel(
    const float* __restrict__ he,
    const int* __restrict__ edst, const float* __restrict__ evec,
    const float* __restrict__ emb, const float* __restrict__ enorm,
    const float* __restrict__ fc2W1, const float* __restrict__ fc2W2,
    float* __restrict__ out_he, int E)
{
    const float SQ3f    = 1.7320508075688772f;
    const float INVSQ3f = 0.57735026918962576f;
    const float RS10    = 0.31622776601683794f;
    const float CS2     = 0.25f;
    const float CV2     = 0.35355339059327379f;

    __shared__ __align__(16) float sW1b[160];
    __shared__ __align__(16) float sW2b[2304];
    {
        const float4* g1b = (const float4*)fc2W1;
        float4* d1b = (float4*)sW1b;
        for (int t = threadIdx.x; t < 40; t += 128) {
            float4 b = g1b[t]; d1b[t] = make_float4(b.x*RS10, b.y*RS10, b.z*RS10, b.w*RS10);
        }
        const float4* g2b = (const float4*)fc2W2;
        float4* d2b = (float4*)sW2b;
        const float sS = CS2 * 0.25f, sV = CV2 * 0.25f;
        for (int t = threadIdx.x; t < 576; t += 128) {
            int c0 = (t*4) % 144;
            float sc = (c0 < 64) ? sS : (c0 < 96) ? sV : (c0 < 128) ? sS : sV;
            float4 a = g2b[t]; d2b[t] = make_float4(a.x*sc, a.y*sc, a.z*sc, a.w*sc);
        }
    }
    __syncthreads();

    int e = blockIdx.x*128 + threadIdx.x;
    if (e >= E) return;

    // load gated intermediates
    float ts[8], tv[12];
    {
        float4 r[5];
        const float4* tp = (const float4*)(g_tmp + (size_t)e*20);
#pragma unroll
        for (int i = 0; i < 5; i++) r[i] = tp[i];
        const float* f = (const float*)r;
#pragma unroll
        for (int j = 0; j < 8; j++) ts[j] = f[j];
#pragma unroll
        for (int j = 0; j < 12; j++) tv[j] = f[8+j];
    }

    float sh1[3];
    {
        float ex = evec[e*3+0], ey = evec[e*3+1], ez = evec[e*3+2];
        float nn = sqrtf(ex*ex + ey*ey + ez*ez) + 1e-12f;
        float f = SQ3f / nn;
        sh1[0] = ex*f; sh1[1] = ey*f; sh1[2] = ez*f;
    }
    float dt[4];
#pragma unroll
    for (int i = 0; i < 4; i++)
        dt[i] = (tv[i*3+0]*sh1[0] + tv[i*3+1]*sh1[1] + tv[i*3+2]*sh1[2]) * INVSQ3f;

    // ---- h2 ----
    u64 h2p[16];
    {
        float embr[10];
        const float2* pe2 = (const float2*)(emb + (size_t)e*10);
#pragma unroll
        for (int j = 0; j < 5; j++) { float2 t = pe2[j]; embr[2*j] = t.x; embr[2*j+1] = t.y; }
        const ulonglong2* W = (const ulonglong2*)sW1b;
        u64 acc[8];
#pragma unroll
        for (int p = 0; p < 8; p++) acc[p] = 0ull;
#pragma unroll
        for (int j = 0; j < 10; j++) {
            u64 ej = pack2(embr[j]);
#pragma unroll
            for (int g = 0; g < 4; g++) {
                ulonglong2 w = W[j*4+g];
                acc[2*g]   = fma2(ej, w.x, acc[2*g]);
                acc[2*g+1] = fma2(ej, w.y, acc[2*g+1]);
            }
        }
#pragma unroll
        for (int p = 0; p < 8; p++) {
            float2 f = unpack2(acc[p]);
            h2p[2*p]   = pack2(fmaxf(f.x, 0.f));
            h2p[2*p+1] = pack2(fmaxf(f.y, 0.f));
        }
    }

    // ---- TP2 (fully unrolled), shared out0 accumulators ----
    const ulonglong2* W2b = (const ulonglong2*)sW2b;  // 36 chunks per k-row
    u64 b0p[4], bsvp[2], b1p[2][3];
#pragma unroll
    for (int p = 0; p < 4; p++) b0p[p] = 0ull;
    bsvp[0] = 0ull; bsvp[1] = 0ull;
#pragma unroll
    for (int c = 0; c < 3; c++) { b1p[0][c] = 0ull; b1p[1][c] = 0ull; }

    // ss: chunk i*2 + g
#pragma unroll
    for (int i = 0; i < 8; i++) {
        u64 si2 = pack2(ts[i]);
#pragma unroll
        for (int g = 0; g < 2; g++) {
            u64 aA = 0ull, aB = 0ull;
#pragma unroll
            for (int k = 0; k < 16; k++) {
                ulonglong2 w = W2b[k*36 + i*2 + g];
                aA = fma2(h2p[k], w.x, aA);
                aB = fma2(h2p[k], w.y, aB);
            }
            b0p[2*g]   = fma2(si2, aA, b0p[2*g]);
            b0p[2*g+1] = fma2(si2, aB, b0p[2*g+1]);
        }
    }
    // vs: chunk 16 + i*2 + g (accumulates into b0p)
#pragma unroll
    for (int i = 0; i < 4; i++) {
        u64 di2 = pack2(dt[i]);
#pragma unroll
        for (int g = 0; g < 2; g++) {
            u64 aA = 0ull, aB = 0ull;
#pragma unroll
            for (int k = 0; k < 16; k++) {
                ulonglong2 w = W2b[k*36 + 16 + i*2 + g];
                aA = fma2(h2p[k], w.x, aA);
                aB = fma2(h2p[k], w.y, aB);
            }
            b0p[2*g]   = fma2(di2, aA, b0p[2*g]);
            b0p[2*g+1] = fma2(di2, aB, b0p[2*g+1]);
        }
    }
    // sv: chunk 24 + i
#pragma unroll
    for (int i = 0; i < 8; i++) {
        u64 aA = 0ull, aB = 0ull;
#pragma unroll
        for (int k = 0; k < 16; k++) {
            ulonglong2 w = W2b[k*36 + 24 + i];
            aA = fma2(h2p[k], w.x, aA);
            aB = fma2(h2p[k], w.y, aB);
        }
        u64 si2 = pack2(ts[i]);
        bsvp[0] = fma2(si2, aA, bsvp[0]);
        bsvp[1] = fma2(si2, aB, bsvp[1]);
    }
    // vv: chunk 32 + i
#pragma unroll
    for (int i = 0; i < 4; i++) {
        u64 aA = 0ull, aB = 0ull;
#pragma unroll
        for (int k = 0; k < 16; k++) {
            ulonglong2 w = W2b[k*36 + 32 + i];
            aA = fma2(h2p[k], w.x, aA);
            aB = fma2(h2p[k], w.y, aB);
        }
#pragma unroll
        for (int c = 0; c < 3; c++) {
            u64 vc2 = pack2(tv[i*3+c]);
            b1p[0][c] = fma2(vc2, aA, b1p[0][c]);
            b1p[1][c] = fma2(vc2, aB, b1p[1][c]);
        }
    }

    // ---- epilogue (scales folded) ----
    float b0[8], bsv[4], b1[4][3];
#pragma unroll
    for (int p = 0; p < 4; p++) {
        float2 f = unpack2(b0p[p]);
        b0[2*p] = f.x; b0[2*p+1] = f.y;
    }
    {
        float2 f0 = unpack2(bsvp[0]); float2 f1 = unpack2(bsvp[1]);
        bsv[0] = f0.x; bsv[1] = f0.y; bsv[2] = f1.x; bsv[3] = f1.y;
    }
#pragma unroll
    for (int c = 0; c < 3; c++) {
        float2 f0 = unpack2(b1p[0][c]); float2 f1 = unpack2(b1p[1][c]);
        b1[0][c] = f0.x; b1[1][c] = f0.y; b1[2][c] = f1.x; b1[3][c] = f1.y;
    }

    float hnew[20];
    {
        float4 r[5];
        const float4* p = (const float4*)(he + (size_t)e*20);
#pragma unroll
        for (int i = 0; i < 5; i++) r[i] = p[i];
        const float* re = (const float*)r;
#pragma unroll
        for (int j = 0; j < 8; j++) hnew[j] = re[j] + b0[j];
#pragma unroll
        for (int o = 0; o < 4; o++)
#pragma unroll
            for (int c = 0; c < 3; c++)
                hnew[8 + o*3 + c] = re[8+o*3+c] + (bsv[o]*sh1[c] + b1[o][c]);
    }

    {
        float4* op = (float4*)(out_he + (size_t)e*20);
        const float4* hp = (const float4*)hnew;
#pragma unroll
        for (int t = 0; t < 5; t++) op[t] = hp[t];
    }
    int dstI = edst[e];
    float nw = enorm[e];
    float* nf = &g_nodeftr[(size_t)dstI*20];
#pragma unroll
    for (int t = 0; t < 5; t++)
        red4(nf + t*4, hnew[t*4]*nw, hnew[t*4+1]*nw, hnew[t*4+2]*nw, hnew[t*4+3]*nw);
}

// ============================ node kernel (also re-zeroes g_nodeftr) ============================
__global__ __launch_bounds__(32) void node_kernel(
    const float* __restrict__ hn,
    const float* __restrict__ WgS, const float* __restrict__ WgV,
    const float* __restrict__ WoS, const float* __restrict__ WoV,
    float* __restrict__ out_hn, int N)
{
    const float RS8 = 0.35355339059327379f;
    int n = blockIdx.x*32 + threadIdx.x;
    if (n >= N) return;

    float cs[16], cv[8][3];
    const float* ph = hn + (size_t)n*20;
    float* pf = g_nodeftr + (size_t)n*20;
#pragma unroll
    for (int j = 0; j < 8; j++) { cs[j] = ph[j]; cs[8+j] = pf[j]; }
#pragma unroll
    for (int i = 0; i < 4; i++)
#pragma unroll
        for (int c = 0; c < 3; c++) { cv[i][c] = ph[8+i*3+c]; cv[4+i][c] = pf[8+i*3+c]; }

    // re-zero for the next launch (loads above already in registers)
    {
        float4 z4 = make_float4(0.f, 0.f, 0.f, 0.f);
        float4* pz = (float4*)pf;
#pragma unroll
        for (int t = 0; t < 5; t++) pz[t] = z4;
    }

    float gl[12];
#pragma unroll
    for (int o = 0; o < 12; o++) {
        float a = 0.f;
#pragma unroll
        for (int i = 0; i < 16; i++) a = fmaf(cs[i], __ldg(&WgS[i*12+o]), a);
        gl[o] = a * 0.25f;
    }
    float vl[4][3];
#pragma unroll
    for (int o = 0; o < 4; o++)
#pragma unroll
        for (int c = 0; c < 3; c++) {
            float a = 0.f;
#pragma unroll
            for (int i = 0; i < 8; i++) a = fmaf(cv[i][c], __ldg(&WgV[i*4+o]), a);
            vl[o][c] = a * RS8;
        }

    float ls[8], lg[4];
#pragma unroll
    for (int j = 0; j < 8; j++) ls[j] = fmaxf(gl[j], 0.f);
#pragma unroll
    for (int o = 0; o < 4; o++) lg[o] = fmaxf(gl[8+o], 0.f);

    float lv[4][3];
#pragma unroll
    for (int o = 0; o < 4; o++)
#pragma unroll
        for (int c = 0; c < 3; c++) lv[o][c] = vl[o][c] * lg[o];

    float os_[8];
#pragma unroll
    for (int o = 0; o < 8; o++) {
        float a = 0.f;
#pragma unroll
        for (int i = 0; i < 8; i++) a = fmaf(ls[i], __ldg(&WoS[i*8+o]), a);
        os_[o] = a * RS8;
    }
    float ov[4][3];
#pragma unroll
    for (int o = 0; o < 4; o++)
#pragma unroll
        for (int c = 0; c < 3; c++) {
            float a = 0.f;
#pragma unroll
            for (int i = 0; i < 4; i++) a = fmaf(lv[i][c], __ldg(&WoV[i*4+o]), a);
            ov[o][c] = a * 0.5f;
        }

    float* po = out_hn + (size_t)n*20;
#pragma unroll
    for (int j = 0; j < 8; j++) po[j] = ph[j] + os_[j];
#pragma unroll
    for (int o = 0; o < 4; o++)
#pragma unroll
        for (int c = 0; c < 3; c++) po[8+o*3+c] = ph[8+o*3+c] + ov[o][c];
}

extern "C" void kernel_launch(void* const* d_in, const int* in_sizes, int n_in,
                              void* d_out, int out_size) {
    const float* hn    = (const float*)d_in[0];
    const float* he    = (const float*)d_in[1];
    const int*   esrc  = (const int*)d_in[2];
    const int*   edst  = (const int*)d_in[3];
    const float* evec  = (const float*)d_in[4];
    const float* emb   = (const float*)d_in[5];
    const float* enorm = (const float*)d_in[6];
    const float* fcW1  = (const float*)d_in[8];
    const float* fcW2  = (const float*)d_in[9];
    const float* fc2W1 = (const float*)d_in[10];
    const float* fc2W2 = (const float*)d_in[11];
    const float* WgS   = (const float*)d_in[12];
    const float* WgV   = (const float*)d_in[13];
    const float* WoS   = (const float*)d_in[14];
    const float* WoV   = (const float*)d_in[15];

    int N = in_sizes[0] / 20;
    int E = in_sizes[1] / 20;

    float* out    = (float*)d_out;
    float* out_hn = out;                      // (N,20) first
    float* out_he = out + (size_t)N * 20;     // (E,20) second

    // g_nodeftr is zero at first call (static init) and re-zeroed by node_kernel
    // at the end of every launch, so no separate zero kernel is needed.
    edge_tp1_kernel<<<(E + 127)/128, 128>>>(hn, he, esrc, edst, evec, emb, fcW1, fcW2, E);
    edge_tp2_kernel<<<(E + 127)/128, 128>>>(he, edst, evec, emb, enorm, fc2W1, fc2W2, out_he, E);
    node_kernel<<<(N + 31)/32, 32>>>(hn, WgS, WgV, WoS, WoV, out_hn, N);
}